// round 3
// baseline (speedup 1.0000x reference)
#include <cuda_runtime.h>
#include <math.h>

#define NSEQ 80
#define SW 256
#define C 128
#define NH 8
#define DH 16
#define FF 512
#define NTOK (NSEQ*SW)          // 20480
#define TOKC (NTOK*C)           // 2621440

#define OUT_L 0
#define OUT_R TOKC
#define RAW_L (2*TOKC)
#define RAW_R (2*TOKC + NSEQ*SW*SW*NH)

typedef unsigned long long ull;

// Scratch (device globals: allocation-free)
__device__ float g_k[2][TOKC];
__device__ float g_q[2][TOKC];
__device__ float g_v[2][TOKC];
__device__ float g_msg[2][TOKC];
__device__ float g_w1p[128*512];   // W1 k-pair interleaved: [kk][j][2]
__device__ float g_w2p[512*128];   // W2 k-pair interleaved: [kk][j][2]

// ---- packed f32x2 helpers (double-rate fp32 on sm_103a, PTX-only) ----
__device__ __forceinline__ void fma2(ull& d, ull a, ull b) {
    asm("fma.rn.f32x2 %0, %1, %2, %3;" : "=l"(d) : "l"(a), "l"(b), "l"(d));
}
__device__ __forceinline__ ull pack2(float x, float y) {
    ull r; asm("mov.b64 %0, {%1, %2};" : "=l"(r) : "f"(x), "f"(y)); return r;
}
__device__ __forceinline__ void unpack2(ull v, float& x, float& y) {
    asm("mov.b64 {%0, %1}, %2;" : "=f"(x), "=f"(y) : "l"(v));
}

// ---------------------------------------------------------------------------
// Kernel 0: interleave W1/W2 k-pairs so GEMM b-operands load as packed pairs.
// ---------------------------------------------------------------------------
__global__ __launch_bounds__(256) void prep_kernel(
    const float* __restrict__ w1, const float* __restrict__ w2)
{
    int i = blockIdx.x * 256 + threadIdx.x;      // 0..32767
    {   // W1: 128x512 -> [64][512][2]
        int kk = i >> 9, j = i & 511;
        ((float2*)g_w1p)[kk*512 + j] =
            make_float2(w1[(2*kk)*FF + j], w1[(2*kk+1)*FF + j]);
    }
    {   // W2: 512x128 -> [256][128][2]
        int kk = i >> 7, j = i & 127;
        ((float2*)g_w2p)[kk*128 + j] =
            make_float2(w2[(2*kk)*C + j], w2[(2*kk+1)*C + j]);
    }
}

// ---------------------------------------------------------------------------
// Kernel 1: per-head KQV projection with coalesced smem-staged stores.
// ---------------------------------------------------------------------------
__global__ __launch_bounds__(256) void proj_kernel(
    const float* __restrict__ feat_l, const float* __restrict__ feat_r,
    const float* __restrict__ kqv_w)
{
    __shared__ float sW[16*48];
    __shared__ float sO[8*548];     // [h][row][d], pitch17, h-stride 548: conflict-free
    int tid = threadIdx.x;
    for (int i = tid; i < 16*48; i += 256) sW[i] = kqv_w[i];

    int side = blockIdx.y;
    const float* feat = side ? feat_r : feat_l;
    int rl = tid >> 3;
    int h  = tid & 7;
    int row = blockIdx.x * 32 + rl;
    __syncthreads();

    float x[16];
    const float4* xp = (const float4*)(feat + (long)row*C + h*DH);
#pragma unroll
    for (int i = 0; i < 4; i++) {
        float4 t = xp[i];
        x[4*i+0]=t.x; x[4*i+1]=t.y; x[4*i+2]=t.z; x[4*i+3]=t.w;
    }
    float o[48];
#pragma unroll
    for (int j = 0; j < 48; j++) o[j] = 0.f;
#pragma unroll
    for (int i = 0; i < 16; i++) {
        float xi = x[i];
#pragma unroll
        for (int j = 0; j < 48; j++) o[j] = fmaf(xi, sW[i*48+j], o[j]);
    }

    int nn = row >> 8;
    int s0 = (blockIdx.x * 32) & 255;
    float* gdst[3] = { g_k[side], g_q[side], g_v[side] };

#pragma unroll
    for (int a = 0; a < 3; a++) {
        __syncthreads();
#pragma unroll
        for (int d = 0; d < 16; d++) sO[h*548 + rl*17 + d] = o[a*16 + d];
        __syncthreads();
        float* gp = gdst[a] + (((long)(nn*NH))*SW + s0) * DH;
        for (int j = tid; j < 4096; j += 256) {
            int hh = j >> 9, rem = j & 511, ss = rem >> 4, d = rem & 15;
            gp[(long)hh*SW*DH + ss*DH + d] = sO[hh*548 + ss*17 + d];
        }
    }
}

// ---------------------------------------------------------------------------
// Kernel 2: cross attention, single pass (no max: scores ~N(0,1) post-temp).
// block = (l-tile 32, n, side). thread = (l,h). f32x2 packed dot + AV.
// ---------------------------------------------------------------------------
__global__ __launch_bounds__(256) void attn_kernel(
    const float* __restrict__ prev_l, const float* __restrict__ prev_r,
    float* __restrict__ d_out)
{
    __shared__ float sK[32*160];
    __shared__ float sV[32*160];
    int tid  = threadIdx.x;
    int nn   = blockIdx.y;
    int side = blockIdx.z;
    int l_loc = tid >> 3;
    int h     = tid & 7;
    int l = blockIdx.x*32 + l_loc;

    const float* prev = side ? prev_r : prev_l;
    float* raw = d_out + (side ? RAW_R : RAW_L);
    const float* qb = g_q[side];
    const float* kb = g_k[side ^ 1];
    const float* vb = g_v[side ^ 1];

    ull q2[8];
    {
        const ull* qp = (const ull*)(qb + (((long)(nn*NH+h))*SW + l)*DH);
#pragma unroll
        for (int i = 0; i < 8; i++) q2[i] = qp[i];
    }
    long pr_base = ((long)(nn*SW + l)*SW)*NH + h;

    float z = 0.f;
    ull acc[8];
#pragma unroll
    for (int i = 0; i < 8; i++) acc[i] = 0ull;

    for (int sc = 0; sc < 8; sc++) {
        int s0 = sc*32;
        for (int j = tid; j < 1024; j += 256) {
            int hh = j >> 7, ss = (j >> 2) & 31, d4 = j & 3;
            long gi = (((long)(nn*NH+hh))*SW + s0+ss)*DH + d4*4;
            *(float4*)(&sK[ss*160 + hh*20 + d4*4]) = *(const float4*)(kb + gi);
            *(float4*)(&sV[ss*160 + hh*20 + d4*4]) = *(const float4*)(vb + gi);
        }
        __syncthreads();
#pragma unroll 4
        for (int s = 0; s < 32; s++) {
            const ull* kd = (const ull*)&sK[s*160 + h*20];
            ull d2 = 0ull;
#pragma unroll
            for (int i = 0; i < 8; i++) fma2(d2, q2[i], kd[i]);
            float dlo, dhi; unpack2(d2, dlo, dhi);
            long idx = pr_base + (long)(s0+s)*NH;
            float r = (dlo + dhi) + __ldcs(prev + idx);
            __stcs(raw + idx, r);
            float e = __expf(0.25f * r);
            z += e;
            ull e2 = pack2(e, e);
            const ull* vd = (const ull*)&sV[s*160 + h*20];
#pragma unroll
            for (int i = 0; i < 8; i++) fma2(acc[i], e2, vd[i]);
        }
        __syncthreads();
    }
    float inv = 1.f / z;
    float om[16];
#pragma unroll
    for (int i = 0; i < 8; i++) {
        float a, b; unpack2(acc[i], a, b);
        om[2*i] = a*inv; om[2*i+1] = b*inv;
    }
    float* mp = g_msg[side] + ((long)(nn*SW + l))*C + h*DH;
#pragma unroll
    for (int i = 0; i < 4; i++)
        *(float4*)(mp + 4*i) = make_float4(om[4*i], om[4*i+1], om[4*i+2], om[4*i+3]);
}

// ---------------------------------------------------------------------------
// Kernel 3: fused LN1 + FFN + residual + LN2, f32x2 k-paired GEMMs.
// ---------------------------------------------------------------------------
#define XPITCH 132
#define HPITCH 516

__global__ __launch_bounds__(256, 1) void ffn_kernel(
    const float* __restrict__ feat_l, const float* __restrict__ feat_r,
    const float* __restrict__ b1, const float* __restrict__ b2,
    const float* __restrict__ lg1, const float* __restrict__ lb1,
    const float* __restrict__ lg2, const float* __restrict__ lb2,
    float* __restrict__ d_out)
{
    extern __shared__ float smem[];
    float* sX = smem;                 // 32 x 132 (LN1 output, residual source)
    float* sH = smem + 32*XPITCH;     // 32 x 516 (gelu output; reused as out tile)
    int tid  = threadIdx.x;
    int side = blockIdx.y;
    const float* feat = side ? feat_r : feat_l;
    const float* msg  = g_msg[side];
    float* outp = d_out + (side ? OUT_R : OUT_L);
    int row0 = blockIdx.x * 32;
    int warp = tid >> 5, lane = tid & 31;

    // load feat + msg
    for (int j = tid; j < 1024; j += 256) {
        int r = j >> 5, c4 = j & 31;
        long gi = ((long)(row0+r))*C + c4*4;
        float4 a = *(const float4*)(feat + gi);
        float4 b = *(const float4*)(msg + gi);
        a.x += b.x; a.y += b.y; a.z += b.z; a.w += b.w;
        *(float4*)(&sX[r*XPITCH + c4*4]) = a;
    }
    __syncthreads();

    // LN1 in place
#pragma unroll
    for (int rr = 0; rr < 4; rr++) {
        int r = warp*4 + rr;
        float v0 = sX[r*XPITCH+lane],    v1 = sX[r*XPITCH+lane+32];
        float v2 = sX[r*XPITCH+lane+64], v3 = sX[r*XPITCH+lane+96];
        float sum = v0+v1+v2+v3;
        float sq  = v0*v0+v1*v1+v2*v2+v3*v3;
        for (int o = 16; o; o >>= 1) {
            sum += __shfl_xor_sync(~0u, sum, o);
            sq  += __shfl_xor_sync(~0u, sq,  o);
        }
        float mu = sum*(1.f/128.f);
        float rs = rsqrtf(sq*(1.f/128.f) - mu*mu + 1e-5f);
        sX[r*XPITCH+lane]    = (v0-mu)*rs*lg1[lane]    + lb1[lane];
        sX[r*XPITCH+lane+32] = (v1-mu)*rs*lg1[lane+32] + lb1[lane+32];
        sX[r*XPITCH+lane+64] = (v2-mu)*rs*lg1[lane+64] + lb1[lane+64];
        sX[r*XPITCH+lane+96] = (v3-mu)*rs*lg1[lane+96] + lb1[lane+96];
    }
    __syncthreads();

    // GEMM1: H[32,512] = X @ W1, k-paired f32x2. thread = 8 rows x 8 cols.
    {
        int cg = tid & 63, rg = tid >> 6;
        ull acc[8][8];
#pragma unroll
        for (int i = 0; i < 8; i++)
#pragma unroll
            for (int j = 0; j < 8; j++) acc[i][j] = 0ull;
#pragma unroll 2
        for (int kk = 0; kk < 64; kk++) {
            ull xr[8];
#pragma unroll
            for (int i = 0; i < 8; i++)
                xr[i] = *(const ull*)&sX[(rg*8+i)*XPITCH + 2*kk];
            const ulonglong2* wp = (const ulonglong2*)(g_w1p + (kk*FF + cg*8)*2);
            ulonglong2 wa = wp[0], wb = wp[1], wc = wp[2], wd = wp[3];
            ull bv[8] = {wa.x, wa.y, wb.x, wb.y, wc.x, wc.y, wd.x, wd.y};
#pragma unroll
            for (int i = 0; i < 8; i++)
#pragma unroll
                for (int j = 0; j < 8; j++) fma2(acc[i][j], xr[i], bv[j]);
        }
        // reduce halves + bias + exact gelu, store H tile
#pragma unroll
        for (int i = 0; i < 8; i++) {
#pragma unroll
            for (int j4 = 0; j4 < 2; j4++) {
                float4 o;
                float* po = (float*)&o;
#pragma unroll
                for (int j = 0; j < 4; j++) {
                    float lo, hi; unpack2(acc[i][j4*4+j], lo, hi);
                    float hx = lo + hi + b1[cg*8 + j4*4 + j];
                    po[j] = 0.5f*hx*(1.f + erff(hx*0.70710678118654752f));
                }
                *(float4*)(&sH[(rg*8+i)*HPITCH + cg*8 + j4*4]) = o;
            }
        }
    }
    __syncthreads();

    // GEMM2: O[32,128] = H @ W2, k-paired f32x2. thread = 2 rows x 8 cols.
    {
        int cg2 = tid & 15, rg2 = tid >> 4;
        ull a2[2][8];
#pragma unroll
        for (int i = 0; i < 2; i++)
#pragma unroll
            for (int j = 0; j < 8; j++) a2[i][j] = 0ull;
#pragma unroll 4
        for (int kk = 0; kk < 256; kk++) {
            ull hr[2];
            hr[0] = *(const ull*)&sH[(rg2*2+0)*HPITCH + 2*kk];
            hr[1] = *(const ull*)&sH[(rg2*2+1)*HPITCH + 2*kk];
            const ulonglong2* wp = (const ulonglong2*)(g_w2p + (kk*C + cg2*8)*2);
            ulonglong2 wa = wp[0], wb = wp[1], wc = wp[2], wd = wp[3];
            ull bv[8] = {wa.x, wa.y, wb.x, wb.y, wc.x, wc.y, wd.x, wd.y};
#pragma unroll
            for (int i = 0; i < 2; i++)
#pragma unroll
                for (int j = 0; j < 8; j++) fma2(a2[i][j], hr[i], bv[j]);
        }
        __syncthreads();   // all GEMM2 reads of sH done; reuse as out tile
#pragma unroll
        for (int i = 0; i < 2; i++) {
            int r = rg2*2 + i;
#pragma unroll
            for (int j4 = 0; j4 < 2; j4++) {
                float4 o;
                float* po = (float*)&o;
#pragma unroll
                for (int j = 0; j < 4; j++) {
                    int col = cg2*8 + j4*4 + j;
                    float lo, hi; unpack2(a2[i][j4*4+j], lo, hi);
                    po[j] = sX[r*XPITCH + col] + lo + hi + b2[col];
                }
                *(float4*)(&sH[r*XPITCH + cg2*8 + j4*4]) = o;
            }
        }
    }
    __syncthreads();

    // LN2 + write out
#pragma unroll
    for (int rr = 0; rr < 4; rr++) {
        int r = warp*4 + rr;
        float v0 = sH[r*XPITCH+lane],    v1 = sH[r*XPITCH+lane+32];
        float v2 = sH[r*XPITCH+lane+64], v3 = sH[r*XPITCH+lane+96];
        float sum = v0+v1+v2+v3;
        float sq  = v0*v0+v1*v1+v2*v2+v3*v3;
        for (int o = 16; o; o >>= 1) {
            sum += __shfl_xor_sync(~0u, sum, o);
            sq  += __shfl_xor_sync(~0u, sq,  o);
        }
        float mu = sum*(1.f/128.f);
        float rs = rsqrtf(sq*(1.f/128.f) - mu*mu + 1e-5f);
        long go = ((long)(row0+r))*C;
        outp[go+lane]    = (v0-mu)*rs*lg2[lane]    + lb2[lane];
        outp[go+lane+32] = (v1-mu)*rs*lg2[lane+32] + lb2[lane+32];
        outp[go+lane+64] = (v2-mu)*rs*lg2[lane+64] + lb2[lane+64];
        outp[go+lane+96] = (v3-mu)*rs*lg2[lane+96] + lb2[lane+96];
    }
}

// ---------------------------------------------------------------------------
extern "C" void kernel_launch(void* const* d_in, const int* in_sizes, int n_in,
                              void* d_out, int out_size)
{
    const float* feat_l = (const float*)d_in[0];
    const float* feat_r = (const float*)d_in[1];
    const float* prev_l = (const float*)d_in[2];
    const float* prev_r = (const float*)d_in[3];
    const float* kqv_w  = (const float*)d_in[4];
    const float* ff_w1  = (const float*)d_in[5];
    const float* ff_b1  = (const float*)d_in[6];
    const float* ff_w2  = (const float*)d_in[7];
    const float* ff_b2  = (const float*)d_in[8];
    const float* ln1_g  = (const float*)d_in[9];
    const float* ln1_b  = (const float*)d_in[10];
    const float* ln2_g  = (const float*)d_in[11];
    const float* ln2_b  = (const float*)d_in[12];
    float* out = (float*)d_out;

    const int FFN_SMEM = (32*XPITCH + 32*HPITCH) * 4;   // 82944 B
    cudaFuncSetAttribute(ffn_kernel, cudaFuncAttributeMaxDynamicSharedMemorySize, FFN_SMEM);

    prep_kernel<<<128, 256>>>(ff_w1, ff_w2);
    proj_kernel<<<dim3(NTOK/32, 2), 256>>>(feat_l, feat_r, kqv_w);
    attn_kernel<<<dim3(SW/32, NSEQ, 2), 256>>>(prev_l, prev_r, out);
    ffn_kernel<<<dim3(NTOK/32, 2), 256, FFN_SMEM>>>(
        feat_l, feat_r, ff_b1, ff_b2,
        ln1_g, ln1_b, ln2_g, ln2_b, out);
}

// round 4
// speedup vs baseline: 1.2718x; 1.2718x over previous
#include <cuda_runtime.h>
#include <math.h>

#define NSEQ 80
#define SW 256
#define C 128
#define NH 8
#define DH 16
#define FF 512
#define NTOK (NSEQ*SW)          // 20480
#define TOKC (NTOK*C)           // 2621440

#define OUT_L 0
#define OUT_R TOKC
#define RAW_L (2*TOKC)
#define RAW_R (2*TOKC + NSEQ*SW*SW*NH)

typedef unsigned long long ull;

// Scratch (device globals: allocation-free)
__device__ float g_k[2][TOKC];
__device__ float g_q[2][TOKC];
__device__ float g_v[2][TOKC];
__device__ float g_msg[2][TOKC];

// ---- packed f32x2 helpers (sm_103a, PTX-only) ----
__device__ __forceinline__ void fma2(ull& d, ull a, ull b) {
    asm("fma.rn.f32x2 %0, %1, %2, %3;" : "=l"(d) : "l"(a), "l"(b), "l"(d));
}
__device__ __forceinline__ ull pack2(float x, float y) {
    ull r; asm("mov.b64 %0, {%1, %2};" : "=l"(r) : "f"(x), "f"(y)); return r;
}
__device__ __forceinline__ void unpack2(ull v, float& x, float& y) {
    asm("mov.b64 {%0, %1}, %2;" : "=f"(x), "=f"(y) : "l"(v));
}

// ---------------------------------------------------------------------------
// Kernel 1: per-head KQV projection with coalesced smem-staged stores.
// ---------------------------------------------------------------------------
__global__ __launch_bounds__(256) void proj_kernel(
    const float* __restrict__ feat_l, const float* __restrict__ feat_r,
    const float* __restrict__ kqv_w)
{
    __shared__ float sW[16*48];
    __shared__ float sO[8*548];     // [h][row][d], pitch17: conflict-free
    int tid = threadIdx.x;
    for (int i = tid; i < 16*48; i += 256) sW[i] = kqv_w[i];

    int side = blockIdx.y;
    const float* feat = side ? feat_r : feat_l;
    int rl = tid >> 3;
    int h  = tid & 7;
    int row = blockIdx.x * 32 + rl;
    __syncthreads();

    float x[16];
    const float4* xp = (const float4*)(feat + (long)row*C + h*DH);
#pragma unroll
    for (int i = 0; i < 4; i++) {
        float4 t = xp[i];
        x[4*i+0]=t.x; x[4*i+1]=t.y; x[4*i+2]=t.z; x[4*i+3]=t.w;
    }
    float o[48];
#pragma unroll
    for (int j = 0; j < 48; j++) o[j] = 0.f;
#pragma unroll
    for (int i = 0; i < 16; i++) {
        float xi = x[i];
#pragma unroll
        for (int j = 0; j < 48; j++) o[j] = fmaf(xi, sW[i*48+j], o[j]);
    }

    int nn = row >> 8;
    int s0 = (blockIdx.x * 32) & 255;
    float* gdst[3] = { g_k[side], g_q[side], g_v[side] };

#pragma unroll
    for (int a = 0; a < 3; a++) {
        __syncthreads();
#pragma unroll
        for (int d = 0; d < 16; d++) sO[h*548 + rl*17 + d] = o[a*16 + d];
        __syncthreads();
        float* gp = gdst[a] + (((long)(nn*NH))*SW + s0) * DH;
        for (int j = tid; j < 4096; j += 256) {
            int hh = j >> 9, rem = j & 511, ss = rem >> 4, d = rem & 15;
            gp[(long)hh*SW*DH + ss*DH + d] = sO[hh*548 + ss*17 + d];
        }
    }
}

// ---------------------------------------------------------------------------
// Kernel 2: cross attention, single pass. block = (64 l, n, side), 512 thr.
// thread = (l,h); f32x2 packed along d (natural pairs both sides).
// ---------------------------------------------------------------------------
__global__ __launch_bounds__(512) void attn_kernel(
    const float* __restrict__ prev_l, const float* __restrict__ prev_r,
    float* __restrict__ d_out)
{
    __shared__ float sK[64*160];    // [s][h*20+d]
    __shared__ float sV[64*160];
    int tid  = threadIdx.x;
    int nn   = blockIdx.y;
    int side = blockIdx.z;
    int l_loc = tid >> 3;
    int h     = tid & 7;
    int l = blockIdx.x*64 + l_loc;

    const float* prev = side ? prev_r : prev_l;
    float* raw = d_out + (side ? RAW_R : RAW_L);
    const float* qb = g_q[side];
    const float* kb = g_k[side ^ 1];
    const float* vb = g_v[side ^ 1];

    ull q2[8];
    {
        const ull* qp = (const ull*)(qb + (((long)(nn*NH+h))*SW + l)*DH);
#pragma unroll
        for (int i = 0; i < 8; i++) q2[i] = qp[i];
    }
    long pr_base = ((long)(nn*SW + l)*SW)*NH + h;

    float z = 0.f;
    ull acc[8];
#pragma unroll
    for (int i = 0; i < 8; i++) acc[i] = 0ull;

    for (int sc = 0; sc < 4; sc++) {
        int s0 = sc*64;
        for (int j = tid; j < 2048; j += 512) {
            int hh = j >> 8, ss = (j >> 2) & 63, d4 = j & 3;
            long gi = (((long)(nn*NH+hh))*SW + s0+ss)*DH + d4*4;
            *(float4*)(&sK[ss*160 + hh*20 + d4*4]) = *(const float4*)(kb + gi);
            *(float4*)(&sV[ss*160 + hh*20 + d4*4]) = *(const float4*)(vb + gi);
        }
        __syncthreads();
#pragma unroll 4
        for (int s = 0; s < 64; s++) {
            const ull* kd = (const ull*)&sK[s*160 + h*20];
            ull d2 = 0ull;
#pragma unroll
            for (int i = 0; i < 8; i++) fma2(d2, q2[i], kd[i]);
            float dlo, dhi; unpack2(d2, dlo, dhi);
            long idx = pr_base + (long)(s0+s)*NH;
            float r = (dlo + dhi) + __ldcs(prev + idx);
            __stcs(raw + idx, r);
            float e = __expf(0.25f * r);
            z += e;
            ull e2 = pack2(e, e);
            const ull* vd = (const ull*)&sV[s*160 + h*20];
#pragma unroll
            for (int i = 0; i < 8; i++) fma2(acc[i], e2, vd[i]);
        }
        __syncthreads();
    }
    float inv = 1.f / z;
    float om[16];
#pragma unroll
    for (int i = 0; i < 8; i++) {
        float a, b; unpack2(acc[i], a, b);
        om[2*i] = a*inv; om[2*i+1] = b*inv;
    }
    float* mp = g_msg[side] + ((long)(nn*SW + l))*C + h*DH;
#pragma unroll
    for (int i = 0; i < 4; i++)
        *(float4*)(mp + 4*i) = make_float4(om[4*i], om[4*i+1], om[4*i+2], om[4*i+3]);
}

// ---------------------------------------------------------------------------
// Kernel 3: fused LN1 + FFN + residual + LN2. f32x2 packed along OUTPUT cols:
// accumulators stay 64 regs for 64 outputs; weight pairs load naturally.
// ---------------------------------------------------------------------------
#define XPITCH 132
#define HPITCH 516

__global__ __launch_bounds__(256, 2) void ffn_kernel(
    const float* __restrict__ feat_l, const float* __restrict__ feat_r,
    const float* __restrict__ w1, const float* __restrict__ b1,
    const float* __restrict__ w2, const float* __restrict__ b2,
    const float* __restrict__ lg1, const float* __restrict__ lb1,
    const float* __restrict__ lg2, const float* __restrict__ lb2,
    float* __restrict__ d_out)
{
    extern __shared__ float smem[];
    float* sX = smem;                 // 32 x 132 (LN1 output, residual source)
    float* sH = smem + 32*XPITCH;     // 32 x 516 (gelu out; reused as out tile)
    int tid  = threadIdx.x;
    int side = blockIdx.y;
    const float* feat = side ? feat_r : feat_l;
    const float* msg  = g_msg[side];
    float* outp = d_out + (side ? OUT_R : OUT_L);
    int row0 = blockIdx.x * 32;
    int warp = tid >> 5, lane = tid & 31;

    // load feat + msg
    for (int j = tid; j < 1024; j += 256) {
        int r = j >> 5, c4 = j & 31;
        long gi = ((long)(row0+r))*C + c4*4;
        float4 a = *(const float4*)(feat + gi);
        float4 b = *(const float4*)(msg + gi);
        a.x += b.x; a.y += b.y; a.z += b.z; a.w += b.w;
        *(float4*)(&sX[r*XPITCH + c4*4]) = a;
    }
    __syncthreads();

    // LN1 in place
#pragma unroll
    for (int rr = 0; rr < 4; rr++) {
        int r = warp*4 + rr;
        float v0 = sX[r*XPITCH+lane],    v1 = sX[r*XPITCH+lane+32];
        float v2 = sX[r*XPITCH+lane+64], v3 = sX[r*XPITCH+lane+96];
        float sum = v0+v1+v2+v3;
        float sq  = v0*v0+v1*v1+v2*v2+v3*v3;
        for (int o = 16; o; o >>= 1) {
            sum += __shfl_xor_sync(~0u, sum, o);
            sq  += __shfl_xor_sync(~0u, sq,  o);
        }
        float mu = sum*(1.f/128.f);
        float rs = rsqrtf(sq*(1.f/128.f) - mu*mu + 1e-5f);
        sX[r*XPITCH+lane]    = (v0-mu)*rs*lg1[lane]    + lb1[lane];
        sX[r*XPITCH+lane+32] = (v1-mu)*rs*lg1[lane+32] + lb1[lane+32];
        sX[r*XPITCH+lane+64] = (v2-mu)*rs*lg1[lane+64] + lb1[lane+64];
        sX[r*XPITCH+lane+96] = (v3-mu)*rs*lg1[lane+96] + lb1[lane+96];
    }
    __syncthreads();

    // GEMM1: H[32,512] = X @ W1. thread = 8 rows x 8 cols (4 col-pairs).
    {
        int cg = tid & 63, rg = tid >> 6;
        ull acc[8][4];
#pragma unroll
        for (int i = 0; i < 8; i++)
#pragma unroll
            for (int j = 0; j < 4; j++) acc[i][j] = 0ull;
        const float* xr0 = sX + (rg*8)*XPITCH;
        for (int k = 0; k < 128; k++) {
            ull xd[8];
#pragma unroll
            for (int i = 0; i < 8; i++) {
                float xv = xr0[i*XPITCH + k];       // warp-uniform bcast
                xd[i] = pack2(xv, xv);
            }
            const ulonglong2* wp = (const ulonglong2*)(w1 + (long)k*FF + cg*8);
            ulonglong2 wa = wp[0], wb = wp[1];
            ull bv[4] = {wa.x, wa.y, wb.x, wb.y};
#pragma unroll
            for (int i = 0; i < 8; i++)
#pragma unroll
                for (int j = 0; j < 4; j++) fma2(acc[i][j], xd[i], bv[j]);
        }
        // bias + exact gelu, store H tile
#pragma unroll
        for (int i = 0; i < 8; i++) {
#pragma unroll
            for (int j4 = 0; j4 < 2; j4++) {
                float4 o;
                float* po = (float*)&o;
#pragma unroll
                for (int jp = 0; jp < 2; jp++) {
                    float lo, hi; unpack2(acc[i][j4*2+jp], lo, hi);
                    float h0 = lo + b1[cg*8 + j4*4 + jp*2];
                    float h1 = hi + b1[cg*8 + j4*4 + jp*2 + 1];
                    po[jp*2]   = 0.5f*h0*(1.f + erff(h0*0.70710678118654752f));
                    po[jp*2+1] = 0.5f*h1*(1.f + erff(h1*0.70710678118654752f));
                }
                *(float4*)(&sH[(rg*8+i)*HPITCH + cg*8 + j4*4]) = o;
            }
        }
    }
    __syncthreads();

    // GEMM2: O[32,128] = H @ W2. thread = 2 rows x 8 cols (4 col-pairs).
    {
        int cg2 = tid & 15, rg2 = tid >> 4;
        ull a2[2][4];
#pragma unroll
        for (int i = 0; i < 2; i++)
#pragma unroll
            for (int j = 0; j < 4; j++) a2[i][j] = 0ull;
        const float* hr0 = sH + (rg2*2)*HPITCH;
        for (int k = 0; k < 512; k++) {
            float h0 = hr0[k];                      // warp-uniform bcast
            float h1 = hr0[HPITCH + k];
            ull hd0 = pack2(h0, h0), hd1 = pack2(h1, h1);
            const ulonglong2* wp = (const ulonglong2*)(w2 + (long)k*C + cg2*8);
            ulonglong2 wa = wp[0], wb = wp[1];
            ull bv[4] = {wa.x, wa.y, wb.x, wb.y};
#pragma unroll
            for (int j = 0; j < 4; j++) { fma2(a2[0][j], hd0, bv[j]); fma2(a2[1][j], hd1, bv[j]); }
        }
        __syncthreads();   // all GEMM2 reads of sH done; reuse as out tile
#pragma unroll
        for (int i = 0; i < 2; i++) {
            int r = rg2*2 + i;
#pragma unroll
            for (int j4 = 0; j4 < 2; j4++) {
                float4 o;
                float* po = (float*)&o;
#pragma unroll
                for (int jp = 0; jp < 2; jp++) {
                    int col = cg2*8 + j4*4 + jp*2;
                    float lo, hi; unpack2(a2[i][j4*2+jp], lo, hi);
                    po[jp*2]   = sX[r*XPITCH + col]     + lo + b2[col];
                    po[jp*2+1] = sX[r*XPITCH + col + 1] + hi + b2[col+1];
                }
                *(float4*)(&sH[r*XPITCH + cg2*8 + j4*4]) = o;
            }
        }
    }
    __syncthreads();

    // LN2 + write out
#pragma unroll
    for (int rr = 0; rr < 4; rr++) {
        int r = warp*4 + rr;
        float v0 = sH[r*XPITCH+lane],    v1 = sH[r*XPITCH+lane+32];
        float v2 = sH[r*XPITCH+lane+64], v3 = sH[r*XPITCH+lane+96];
        float sum = v0+v1+v2+v3;
        float sq  = v0*v0+v1*v1+v2*v2+v3*v3;
        for (int o = 16; o; o >>= 1) {
            sum += __shfl_xor_sync(~0u, sum, o);
            sq  += __shfl_xor_sync(~0u, sq,  o);
        }
        float mu = sum*(1.f/128.f);
        float rs = rsqrtf(sq*(1.f/128.f) - mu*mu + 1e-5f);
        long go = ((long)(row0+r))*C;
        outp[go+lane]    = (v0-mu)*rs*lg2[lane]    + lb2[lane];
        outp[go+lane+32] = (v1-mu)*rs*lg2[lane+32] + lb2[lane+32];
        outp[go+lane+64] = (v2-mu)*rs*lg2[lane+64] + lb2[lane+64];
        outp[go+lane+96] = (v3-mu)*rs*lg2[lane+96] + lb2[lane+96];
    }
}

// ---------------------------------------------------------------------------
extern "C" void kernel_launch(void* const* d_in, const int* in_sizes, int n_in,
                              void* d_out, int out_size)
{
    const float* feat_l = (const float*)d_in[0];
    const float* feat_r = (const float*)d_in[1];
    const float* prev_l = (const float*)d_in[2];
    const float* prev_r = (const float*)d_in[3];
    const float* kqv_w  = (const float*)d_in[4];
    const float* ff_w1  = (const float*)d_in[5];
    const float* ff_b1  = (const float*)d_in[6];
    const float* ff_w2  = (const float*)d_in[7];
    const float* ff_b2  = (const float*)d_in[8];
    const float* ln1_g  = (const float*)d_in[9];
    const float* ln1_b  = (const float*)d_in[10];
    const float* ln2_g  = (const float*)d_in[11];
    const float* ln2_b  = (const float*)d_in[12];
    float* out = (float*)d_out;

    const int FFN_SMEM = (32*XPITCH + 32*HPITCH) * 4;   // 82944 B
    cudaFuncSetAttribute(ffn_kernel, cudaFuncAttributeMaxDynamicSharedMemorySize, FFN_SMEM);

    proj_kernel<<<dim3(NTOK/32, 2), 256>>>(feat_l, feat_r, kqv_w);
    attn_kernel<<<dim3(SW/64, NSEQ, 2), 512>>>(prev_l, prev_r, out);
    ffn_kernel<<<dim3(NTOK/32, 2), 256, FFN_SMEM>>>(
        feat_l, feat_r, ff_w1, ff_b1, ff_w2, ff_b2,
        ln1_g, ln1_b, ln2_g, ln2_b, out);
}

// round 5
// speedup vs baseline: 1.9428x; 1.5276x over previous
#include <cuda_runtime.h>
#include <math.h>

#define NSEQ 80
#define SW 256
#define C 128
#define NH 8
#define DH 16
#define FF 512
#define NTOK (NSEQ*SW)          // 20480
#define TOKC (NTOK*C)           // 2621440

#define OUT_L 0
#define OUT_R TOKC
#define RAW_L (2*TOKC)
#define RAW_R (2*TOKC + NSEQ*SW*SW*NH)

// Scratch (device globals: allocation-free)
__device__ float g_k[2][TOKC];
__device__ float g_q[2][TOKC];
__device__ float g_v[2][TOKC];
__device__ float g_msg[2][TOKC];
__device__ float g_w1f[16*32*32*4];   // W1 tf32 frag layout: [ks][tp][lane][4]
__device__ float g_w2f[64*8*32*4];    // W2 tf32 frag layout: [ks][tp][lane][4]

// ---- tf32 mma helpers ----
__device__ __forceinline__ unsigned f2tf32(float x) {
    unsigned r; asm("cvt.rna.tf32.f32 %0, %1;" : "=r"(r) : "f"(x)); return r;
}
__device__ __forceinline__ void mma_tf32(float* c,
    unsigned a0, unsigned a1, unsigned a2, unsigned a3,
    unsigned b0, unsigned b1)
{
    asm("mma.sync.aligned.m16n8k8.row.col.f32.tf32.tf32.f32 "
        "{%0,%1,%2,%3},{%4,%5,%6,%7},{%8,%9},{%0,%1,%2,%3};"
        : "+f"(c[0]), "+f"(c[1]), "+f"(c[2]), "+f"(c[3])
        : "r"(a0), "r"(a1), "r"(a2), "r"(a3), "r"(b0), "r"(b1));
}

// ---------------------------------------------------------------------------
// Kernel 0: W1/W2 -> tf32 fragment layouts.
// Fragment for mma m16n8k8 (B col-major view, B = W[k][n]):
//   lane (gid=l>>2, tig=l&3) holds b0=W[k0+tig][n0+gid], b1=W[k0+tig+4][n0+gid]
// Two adjacent n8 tiles packed per float4: {t0.b0, t0.b1, t1.b0, t1.b1}.
// ---------------------------------------------------------------------------
__global__ __launch_bounds__(256) void prep_kernel(
    const float* __restrict__ w1, const float* __restrict__ w2)
{
    int i = blockIdx.x * 256 + threadIdx.x;     // 0..32767
    if (i < 16384) {        // W1: ks 0..15, tp 0..31, lane 0..31
        int lane = i & 31, tp = (i >> 5) & 31, ks = i >> 10;
        int gid = lane >> 2, tig = lane & 3;
        int k0 = ks*8, n0 = (2*tp)*8, n1 = (2*tp+1)*8;
        float4 o;
        o.x = __uint_as_float(f2tf32(w1[(k0+tig)*FF   + n0+gid]));
        o.y = __uint_as_float(f2tf32(w1[(k0+tig+4)*FF + n0+gid]));
        o.z = __uint_as_float(f2tf32(w1[(k0+tig)*FF   + n1+gid]));
        o.w = __uint_as_float(f2tf32(w1[(k0+tig+4)*FF + n1+gid]));
        ((float4*)g_w1f)[i] = o;
    } else {                // W2: ks 0..63, tp 0..7, lane 0..31
        int j = i - 16384;
        int lane = j & 31, tp = (j >> 5) & 7, ks = j >> 8;
        int gid = lane >> 2, tig = lane & 3;
        int k0 = ks*8, n0 = (2*tp)*8, n1 = (2*tp+1)*8;
        float4 o;
        o.x = __uint_as_float(f2tf32(w2[(k0+tig)*C   + n0+gid]));
        o.y = __uint_as_float(f2tf32(w2[(k0+tig+4)*C + n0+gid]));
        o.z = __uint_as_float(f2tf32(w2[(k0+tig)*C   + n1+gid]));
        o.w = __uint_as_float(f2tf32(w2[(k0+tig+4)*C + n1+gid]));
        ((float4*)g_w2f)[j] = o;
    }
}

// ---------------------------------------------------------------------------
// Kernel 1: per-head KQV projection with coalesced smem-staged stores.
// ---------------------------------------------------------------------------
__global__ __launch_bounds__(256) void proj_kernel(
    const float* __restrict__ feat_l, const float* __restrict__ feat_r,
    const float* __restrict__ kqv_w)
{
    __shared__ float sW[16*48];
    __shared__ float sO[8*548];
    int tid = threadIdx.x;
    for (int i = tid; i < 16*48; i += 256) sW[i] = kqv_w[i];

    int side = blockIdx.y;
    const float* feat = side ? feat_r : feat_l;
    int rl = tid >> 3;
    int h  = tid & 7;
    int row = blockIdx.x * 32 + rl;
    __syncthreads();

    float x[16];
    const float4* xp = (const float4*)(feat + (long)row*C + h*DH);
#pragma unroll
    for (int i = 0; i < 4; i++) {
        float4 t = xp[i];
        x[4*i+0]=t.x; x[4*i+1]=t.y; x[4*i+2]=t.z; x[4*i+3]=t.w;
    }
    float o[48];
#pragma unroll
    for (int j = 0; j < 48; j++) o[j] = 0.f;
#pragma unroll
    for (int i = 0; i < 16; i++) {
        float xi = x[i];
#pragma unroll
        for (int j = 0; j < 48; j++) o[j] = fmaf(xi, sW[i*48+j], o[j]);
    }

    int nn = row >> 8;
    int s0 = (blockIdx.x * 32) & 255;
    float* gdst[3] = { g_k[side], g_q[side], g_v[side] };

#pragma unroll
    for (int a = 0; a < 3; a++) {
        __syncthreads();
#pragma unroll
        for (int d = 0; d < 16; d++) sO[h*548 + rl*17 + d] = o[a*16 + d];
        __syncthreads();
        float* gp = gdst[a] + (((long)(nn*NH))*SW + s0) * DH;
        for (int j = tid; j < 4096; j += 256) {
            int hh = j >> 9, rem = j & 511, ss = rem >> 4, d = rem & 15;
            gp[(long)hh*SW*DH + ss*DH + d] = sO[hh*548 + ss*17 + d];
        }
    }
}

// ---------------------------------------------------------------------------
// Kernel 2: cross attention, single pass, scalar fp32 (raw must be exact).
// ---------------------------------------------------------------------------
__global__ __launch_bounds__(512) void attn_kernel(
    const float* __restrict__ prev_l, const float* __restrict__ prev_r,
    float* __restrict__ d_out)
{
    __shared__ float sK[64*160];
    __shared__ float sV[64*160];
    int tid  = threadIdx.x;
    int nn   = blockIdx.y;
    int side = blockIdx.z;
    int l_loc = tid >> 3;
    int h     = tid & 7;
    int l = blockIdx.x*64 + l_loc;

    const float* prev = side ? prev_r : prev_l;
    float* raw = d_out + (side ? RAW_R : RAW_L);
    const float* qb = g_q[side];
    const float* kb = g_k[side ^ 1];
    const float* vb = g_v[side ^ 1];

    float q[16];
    {
        const float4* qp = (const float4*)(qb + (((long)(nn*NH+h))*SW + l)*DH);
#pragma unroll
        for (int i = 0; i < 4; i++) {
            float4 t = qp[i];
            q[4*i+0]=t.x; q[4*i+1]=t.y; q[4*i+2]=t.z; q[4*i+3]=t.w;
        }
    }
    long pr_base = ((long)(nn*SW + l)*SW)*NH + h;

    float z = 0.f;
    float acc[16];
#pragma unroll
    for (int i = 0; i < 16; i++) acc[i] = 0.f;

    for (int sc = 0; sc < 4; sc++) {
        int s0 = sc*64;
        for (int j = tid; j < 2048; j += 512) {
            int hh = j >> 8, ss = (j >> 2) & 63, d4 = j & 3;
            long gi = (((long)(nn*NH+hh))*SW + s0+ss)*DH + d4*4;
            *(float4*)(&sK[ss*160 + hh*20 + d4*4]) = *(const float4*)(kb + gi);
            *(float4*)(&sV[ss*160 + hh*20 + d4*4]) = *(const float4*)(vb + gi);
        }
        __syncthreads();
#pragma unroll 4
        for (int s = 0; s < 64; s++) {
            const float4* kd = (const float4*)&sK[s*160 + h*20];
            float4 k0 = kd[0], k1 = kd[1], k2 = kd[2], k3 = kd[3];
            float dot = q[0]*k0.x;
            dot = fmaf(q[1],k0.y, dot); dot = fmaf(q[2],k0.z, dot); dot = fmaf(q[3],k0.w, dot);
            dot = fmaf(q[4],k1.x, dot); dot = fmaf(q[5],k1.y, dot); dot = fmaf(q[6],k1.z, dot); dot = fmaf(q[7],k1.w, dot);
            dot = fmaf(q[8],k2.x, dot); dot = fmaf(q[9],k2.y, dot); dot = fmaf(q[10],k2.z, dot); dot = fmaf(q[11],k2.w, dot);
            dot = fmaf(q[12],k3.x, dot); dot = fmaf(q[13],k3.y, dot); dot = fmaf(q[14],k3.z, dot); dot = fmaf(q[15],k3.w, dot);
            long idx = pr_base + (long)(s0+s)*NH;
            float r = dot + __ldcs(prev + idx);
            __stcs(raw + idx, r);
            float e = __expf(0.25f * r);
            z += e;
            const float4* vd = (const float4*)&sV[s*160 + h*20];
            float4 v0 = vd[0], v1 = vd[1], v2 = vd[2], v3 = vd[3];
            acc[0]=fmaf(e,v0.x,acc[0]);  acc[1]=fmaf(e,v0.y,acc[1]);
            acc[2]=fmaf(e,v0.z,acc[2]);  acc[3]=fmaf(e,v0.w,acc[3]);
            acc[4]=fmaf(e,v1.x,acc[4]);  acc[5]=fmaf(e,v1.y,acc[5]);
            acc[6]=fmaf(e,v1.z,acc[6]);  acc[7]=fmaf(e,v1.w,acc[7]);
            acc[8]=fmaf(e,v2.x,acc[8]);  acc[9]=fmaf(e,v2.y,acc[9]);
            acc[10]=fmaf(e,v2.z,acc[10]); acc[11]=fmaf(e,v2.w,acc[11]);
            acc[12]=fmaf(e,v3.x,acc[12]); acc[13]=fmaf(e,v3.y,acc[13]);
            acc[14]=fmaf(e,v3.z,acc[14]); acc[15]=fmaf(e,v3.w,acc[15]);
        }
        __syncthreads();
    }
    float inv = 1.f / z;
    float* mp = g_msg[side] + ((long)(nn*SW + l))*C + h*DH;
#pragma unroll
    for (int i = 0; i < 4; i++)
        *(float4*)(mp + 4*i) = make_float4(acc[4*i]*inv, acc[4*i+1]*inv,
                                           acc[4*i+2]*inv, acc[4*i+3]*inv);
}

// ---------------------------------------------------------------------------
// Kernel 3: fused LN1 + FFN (tf32 mma.sync) + residual + LN2. 32 rows/block.
// ---------------------------------------------------------------------------
#define XPITCH 132
#define HPITCH 516

__global__ __launch_bounds__(256, 2) void ffn_kernel(
    const float* __restrict__ feat_l, const float* __restrict__ feat_r,
    const float* __restrict__ b1, const float* __restrict__ b2,
    const float* __restrict__ lg1, const float* __restrict__ lb1,
    const float* __restrict__ lg2, const float* __restrict__ lb2,
    float* __restrict__ d_out)
{
    extern __shared__ float smem[];
    float* sX = smem;                 // 32 x 132 fp32 (LN1 out / residual)
    float* sH = smem + 32*XPITCH;     // 32 x 516 (tf32-rounded gelu; then out tile)
    int tid  = threadIdx.x;
    int side = blockIdx.y;
    const float* feat = side ? feat_r : feat_l;
    const float* msg  = g_msg[side];
    float* outp = d_out + (side ? OUT_R : OUT_L);
    int row0 = blockIdx.x * 32;
    int warp = tid >> 5, lane = tid & 31;
    int gid = lane >> 2, tig = lane & 3;
    int mt = warp & 1, ng = warp >> 1;
    int m0 = mt*16;

    // load feat + msg
    for (int j = tid; j < 1024; j += 256) {
        int r = j >> 5, c4 = j & 31;
        long gi = ((long)(row0+r))*C + c4*4;
        float4 a = *(const float4*)(feat + gi);
        float4 b = *(const float4*)(msg + gi);
        a.x += b.x; a.y += b.y; a.z += b.z; a.w += b.w;
        *(float4*)(&sX[r*XPITCH + c4*4]) = a;
    }
    __syncthreads();

    // LN1 in place
#pragma unroll
    for (int rr = 0; rr < 4; rr++) {
        int r = warp*4 + rr;
        float v0 = sX[r*XPITCH+lane],    v1 = sX[r*XPITCH+lane+32];
        float v2 = sX[r*XPITCH+lane+64], v3 = sX[r*XPITCH+lane+96];
        float sum = v0+v1+v2+v3;
        float sq  = v0*v0+v1*v1+v2*v2+v3*v3;
        for (int o = 16; o; o >>= 1) {
            sum += __shfl_xor_sync(~0u, sum, o);
            sq  += __shfl_xor_sync(~0u, sq,  o);
        }
        float mu = sum*(1.f/128.f);
        float rs = rsqrtf(sq*(1.f/128.f) - mu*mu + 1e-5f);
        sX[r*XPITCH+lane]    = (v0-mu)*rs*lg1[lane]    + lb1[lane];
        sX[r*XPITCH+lane+32] = (v1-mu)*rs*lg1[lane+32] + lb1[lane+32];
        sX[r*XPITCH+lane+64] = (v2-mu)*rs*lg1[lane+64] + lb1[lane+64];
        sX[r*XPITCH+lane+96] = (v3-mu)*rs*lg1[lane+96] + lb1[lane+96];
    }
    __syncthreads();

    // GEMM1: H[32,512] = X @ W1.  warp: m16 tile mt, cols [ng*128, ng*128+128)
    {
        float acc[16][4];
#pragma unroll
        for (int t = 0; t < 16; t++)
#pragma unroll
            for (int j = 0; j < 4; j++) acc[t][j] = 0.f;

#pragma unroll 2
        for (int ks = 0; ks < 16; ks++) {
            int k0 = ks*8;
            unsigned a0 = f2tf32(sX[(m0+gid)*XPITCH   + k0 + tig]);
            unsigned a1 = f2tf32(sX[(m0+gid+8)*XPITCH + k0 + tig]);
            unsigned a2 = f2tf32(sX[(m0+gid)*XPITCH   + k0 + tig + 4]);
            unsigned a3 = f2tf32(sX[(m0+gid+8)*XPITCH + k0 + tig + 4]);
            const float4* bp = (const float4*)g_w1f + (ks*32 + ng*8)*32 + lane;
#pragma unroll
            for (int tp = 0; tp < 8; tp++) {
                float4 b = bp[tp*32];
                mma_tf32(acc[2*tp],   a0,a1,a2,a3, __float_as_uint(b.x), __float_as_uint(b.y));
                mma_tf32(acc[2*tp+1], a0,a1,a2,a3, __float_as_uint(b.z), __float_as_uint(b.w));
            }
        }
        // bias + gelu + tf32-round, store H
#pragma unroll
        for (int t = 0; t < 16; t++) {
            int col = ng*128 + t*8 + 2*tig;
            float h00 = acc[t][0] + b1[col];
            float h01 = acc[t][1] + b1[col+1];
            float h10 = acc[t][2] + b1[col];
            float h11 = acc[t][3] + b1[col+1];
            h00 = 0.5f*h00*(1.f + erff(h00*0.70710678118654752f));
            h01 = 0.5f*h01*(1.f + erff(h01*0.70710678118654752f));
            h10 = 0.5f*h10*(1.f + erff(h10*0.70710678118654752f));
            h11 = 0.5f*h11*(1.f + erff(h11*0.70710678118654752f));
            float2 lo = make_float2(__uint_as_float(f2tf32(h00)), __uint_as_float(f2tf32(h01)));
            float2 hi = make_float2(__uint_as_float(f2tf32(h10)), __uint_as_float(f2tf32(h11)));
            *(float2*)(&sH[(m0+gid)*HPITCH   + col]) = lo;
            *(float2*)(&sH[(m0+gid+8)*HPITCH + col]) = hi;
        }
    }
    __syncthreads();

    // GEMM2: O[32,128] = H @ W2.  warp: m16 tile mt, cols [ng*32, ng*32+32)
    float acc2[4][4];
#pragma unroll
    for (int t = 0; t < 4; t++)
#pragma unroll
        for (int j = 0; j < 4; j++) acc2[t][j] = 0.f;
    {
        const unsigned* sHi = (const unsigned*)sH;   // tf32 bit patterns
#pragma unroll 4
        for (int ks = 0; ks < 64; ks++) {
            int k0 = ks*8;
            unsigned a0 = sHi[(m0+gid)*HPITCH   + k0 + tig];
            unsigned a1 = sHi[(m0+gid+8)*HPITCH + k0 + tig];
            unsigned a2 = sHi[(m0+gid)*HPITCH   + k0 + tig + 4];
            unsigned a3 = sHi[(m0+gid+8)*HPITCH + k0 + tig + 4];
            const float4* bp = (const float4*)g_w2f + (ks*8 + ng*2)*32 + lane;
            float4 b0v = bp[0];
            float4 b1v = bp[32];
            mma_tf32(acc2[0], a0,a1,a2,a3, __float_as_uint(b0v.x), __float_as_uint(b0v.y));
            mma_tf32(acc2[1], a0,a1,a2,a3, __float_as_uint(b0v.z), __float_as_uint(b0v.w));
            mma_tf32(acc2[2], a0,a1,a2,a3, __float_as_uint(b1v.x), __float_as_uint(b1v.y));
            mma_tf32(acc2[3], a0,a1,a2,a3, __float_as_uint(b1v.z), __float_as_uint(b1v.w));
        }
    }
    __syncthreads();   // all reads of sH done; reuse as out tile (pitch XPITCH)

    // residual + bias, store out tile
#pragma unroll
    for (int t = 0; t < 4; t++) {
        int col = ng*32 + t*8 + 2*tig;
        int r0 = m0+gid, r1 = m0+gid+8;
        float2 lo, hi;
        lo.x = acc2[t][0] + b2[col]   + sX[r0*XPITCH + col];
        lo.y = acc2[t][1] + b2[col+1] + sX[r0*XPITCH + col + 1];
        hi.x = acc2[t][2] + b2[col]   + sX[r1*XPITCH + col];
        hi.y = acc2[t][3] + b2[col+1] + sX[r1*XPITCH + col + 1];
        *(float2*)(&sH[r0*XPITCH + col]) = lo;
        *(float2*)(&sH[r1*XPITCH + col]) = hi;
    }
    __syncthreads();

    // LN2 + write out
#pragma unroll
    for (int rr = 0; rr < 4; rr++) {
        int r = warp*4 + rr;
        float v0 = sH[r*XPITCH+lane],    v1 = sH[r*XPITCH+lane+32];
        float v2 = sH[r*XPITCH+lane+64], v3 = sH[r*XPITCH+lane+96];
        float sum = v0+v1+v2+v3;
        float sq  = v0*v0+v1*v1+v2*v2+v3*v3;
        for (int o = 16; o; o >>= 1) {
            sum += __shfl_xor_sync(~0u, sum, o);
            sq  += __shfl_xor_sync(~0u, sq,  o);
        }
        float mu = sum*(1.f/128.f);
        float rs = rsqrtf(sq*(1.f/128.f) - mu*mu + 1e-5f);
        long go = ((long)(row0+r))*C;
        outp[go+lane]    = (v0-mu)*rs*lg2[lane]    + lb2[lane];
        outp[go+lane+32] = (v1-mu)*rs*lg2[lane+32] + lb2[lane+32];
        outp[go+lane+64] = (v2-mu)*rs*lg2[lane+64] + lb2[lane+64];
        outp[go+lane+96] = (v3-mu)*rs*lg2[lane+96] + lb2[lane+96];
    }
}

// ---------------------------------------------------------------------------
extern "C" void kernel_launch(void* const* d_in, const int* in_sizes, int n_in,
                              void* d_out, int out_size)
{
    const float* feat_l = (const float*)d_in[0];
    const float* feat_r = (const float*)d_in[1];
    const float* prev_l = (const float*)d_in[2];
    const float* prev_r = (const float*)d_in[3];
    const float* kqv_w  = (const float*)d_in[4];
    const float* ff_w1  = (const float*)d_in[5];
    const float* ff_b1  = (const float*)d_in[6];
    const float* ff_w2  = (const float*)d_in[7];
    const float* ff_b2  = (const float*)d_in[8];
    const float* ln1_g  = (const float*)d_in[9];
    const float* ln1_b  = (const float*)d_in[10];
    const float* ln2_g  = (const float*)d_in[11];
    const float* ln2_b  = (const float*)d_in[12];
    float* out = (float*)d_out;

    const int FFN_SMEM = (32*XPITCH + 32*HPITCH) * 4;   // 82944 B
    cudaFuncSetAttribute(ffn_kernel, cudaFuncAttributeMaxDynamicSharedMemorySize, FFN_SMEM);

    prep_kernel<<<128, 256>>>(ff_w1, ff_w2);
    proj_kernel<<<dim3(NTOK/32, 2), 256>>>(feat_l, feat_r, kqv_w);
    attn_kernel<<<dim3(SW/64, NSEQ, 2), 512>>>(prev_l, prev_r, out);
    ffn_kernel<<<dim3(NTOK/32, 2), 256, FFN_SMEM>>>(
        feat_l, feat_r, ff_b1, ff_b2,
        ln1_g, ln1_b, ln2_g, ln2_b, out);
}

// round 6
// speedup vs baseline: 2.3485x; 1.2088x over previous
#include <cuda_runtime.h>
#include <math.h>

#define NSEQ 80
#define SW 256
#define C 128
#define NH 8
#define DH 16
#define FF 512
#define NTOK (NSEQ*SW)          // 20480
#define TOKC (NTOK*C)           // 2621440

#define OUT_L 0
#define OUT_R TOKC
#define RAW_L (2*TOKC)
#define RAW_R (2*TOKC + NSEQ*SW*SW*NH)

// Scratch (device globals: allocation-free)
__device__ float g_k[2][TOKC];
__device__ float g_q[2][TOKC];
__device__ float g_v[2][TOKC];
__device__ float g_msg[2][TOKC];
__device__ float g_w1f[16*32*32*4];   // W1 tf32 frag layout: [ks][tp][lane][4]
__device__ float g_w2f[64*8*32*4];    // W2 tf32 frag layout: [ks][tp][lane][4]

// ---- tf32 mma helpers ----
__device__ __forceinline__ unsigned f2tf32(float x) {
    unsigned r; asm("cvt.rna.tf32.f32 %0, %1;" : "=r"(r) : "f"(x)); return r;
}
__device__ __forceinline__ void mma_tf32(float* c,
    unsigned a0, unsigned a1, unsigned a2, unsigned a3,
    unsigned b0, unsigned b1)
{
    asm("mma.sync.aligned.m16n8k8.row.col.f32.tf32.tf32.f32 "
        "{%0,%1,%2,%3},{%4,%5,%6,%7},{%8,%9},{%0,%1,%2,%3};"
        : "+f"(c[0]), "+f"(c[1]), "+f"(c[2]), "+f"(c[3])
        : "r"(a0), "r"(a1), "r"(a2), "r"(a3), "r"(b0), "r"(b1));
}

// ---------------------------------------------------------------------------
// Kernel 0: W1/W2 -> tf32 fragment layouts.
// ---------------------------------------------------------------------------
__global__ __launch_bounds__(256) void prep_kernel(
    const float* __restrict__ w1, const float* __restrict__ w2)
{
    int i = blockIdx.x * 256 + threadIdx.x;     // 0..32767
    if (i < 16384) {        // W1: ks 0..15, tp 0..31, lane 0..31
        int lane = i & 31, tp = (i >> 5) & 31, ks = i >> 10;
        int gid = lane >> 2, tig = lane & 3;
        int k0 = ks*8, n0 = (2*tp)*8, n1 = (2*tp+1)*8;
        float4 o;
        o.x = __uint_as_float(f2tf32(w1[(k0+tig)*FF   + n0+gid]));
        o.y = __uint_as_float(f2tf32(w1[(k0+tig+4)*FF + n0+gid]));
        o.z = __uint_as_float(f2tf32(w1[(k0+tig)*FF   + n1+gid]));
        o.w = __uint_as_float(f2tf32(w1[(k0+tig+4)*FF + n1+gid]));
        ((float4*)g_w1f)[i] = o;
    } else {                // W2: ks 0..63, tp 0..7, lane 0..31
        int j = i - 16384;
        int lane = j & 31, tp = (j >> 5) & 7, ks = j >> 8;
        int gid = lane >> 2, tig = lane & 3;
        int k0 = ks*8, n0 = (2*tp)*8, n1 = (2*tp+1)*8;
        float4 o;
        o.x = __uint_as_float(f2tf32(w2[(k0+tig)*C   + n0+gid]));
        o.y = __uint_as_float(f2tf32(w2[(k0+tig+4)*C + n0+gid]));
        o.z = __uint_as_float(f2tf32(w2[(k0+tig)*C   + n1+gid]));
        o.w = __uint_as_float(f2tf32(w2[(k0+tig+4)*C + n1+gid]));
        ((float4*)g_w2f)[j] = o;
    }
}

// ---------------------------------------------------------------------------
// Kernel 1: per-head KQV projection with coalesced smem-staged stores.
// ---------------------------------------------------------------------------
__global__ __launch_bounds__(256) void proj_kernel(
    const float* __restrict__ feat_l, const float* __restrict__ feat_r,
    const float* __restrict__ kqv_w)
{
    __shared__ float sW[16*48];
    __shared__ float sO[8*548];
    int tid = threadIdx.x;
    for (int i = tid; i < 16*48; i += 256) sW[i] = kqv_w[i];

    int side = blockIdx.y;
    const float* feat = side ? feat_r : feat_l;
    int rl = tid >> 3;
    int h  = tid & 7;
    int row = blockIdx.x * 32 + rl;
    __syncthreads();

    float x[16];
    const float4* xp = (const float4*)(feat + (long)row*C + h*DH);
#pragma unroll
    for (int i = 0; i < 4; i++) {
        float4 t = xp[i];
        x[4*i+0]=t.x; x[4*i+1]=t.y; x[4*i+2]=t.z; x[4*i+3]=t.w;
    }
    float o[48];
#pragma unroll
    for (int j = 0; j < 48; j++) o[j] = 0.f;
#pragma unroll
    for (int i = 0; i < 16; i++) {
        float xi = x[i];
#pragma unroll
        for (int j = 0; j < 48; j++) o[j] = fmaf(xi, sW[i*48+j], o[j]);
    }

    int nn = row >> 8;
    int s0 = (blockIdx.x * 32) & 255;
    float* gdst[3] = { g_k[side], g_q[side], g_v[side] };

#pragma unroll
    for (int a = 0; a < 3; a++) {
        __syncthreads();
#pragma unroll
        for (int d = 0; d < 16; d++) sO[h*548 + rl*17 + d] = o[a*16 + d];
        __syncthreads();
        float* gp = gdst[a] + (((long)(nn*NH))*SW + s0) * DH;
        for (int j = tid; j < 4096; j += 256) {
            int hh = j >> 9, rem = j & 511, ss = rem >> 4, d = rem & 15;
            gp[(long)hh*SW*DH + ss*DH + d] = sO[hh*548 + ss*17 + d];
        }
    }
}

// ---------------------------------------------------------------------------
// Kernel 2: cross attention, single pass, scalar fp32.
// block = (32 l, n, side), 256 thr = (l,h). prev double-buffered in regs
// (chunks of 16 s, MLP 16) to kill the per-iteration DRAM latency stall.
// ---------------------------------------------------------------------------
__global__ __launch_bounds__(256, 2) void attn_kernel(
    const float* __restrict__ prev_l, const float* __restrict__ prev_r,
    float* __restrict__ d_out)
{
    __shared__ float sK[64*160];    // [s][h*20+d]
    __shared__ float sV[64*160];
    int tid  = threadIdx.x;
    int nn   = blockIdx.y;
    int side = blockIdx.z;
    int l_loc = tid >> 3;
    int h     = tid & 7;
    int l = blockIdx.x*32 + l_loc;

    const float* prev = side ? prev_r : prev_l;
    float* raw = d_out + (side ? RAW_R : RAW_L);
    const float* qb = g_q[side];
    const float* kb = g_k[side ^ 1];
    const float* vb = g_v[side ^ 1];

    float q[16];
    {
        const float4* qp = (const float4*)(qb + (((long)(nn*NH+h))*SW + l)*DH);
#pragma unroll
        for (int i = 0; i < 4; i++) {
            float4 t = qp[i];
            q[4*i+0]=t.x; q[4*i+1]=t.y; q[4*i+2]=t.z; q[4*i+3]=t.w;
        }
    }
    long pr_base = ((long)(nn*SW + l)*SW)*NH + h;

    float pbuf[16];
#pragma unroll
    for (int i = 0; i < 16; i++) pbuf[i] = __ldcs(prev + pr_base + i*NH);

    float z = 0.f;
    float acc[16];
#pragma unroll
    for (int i = 0; i < 16; i++) acc[i] = 0.f;

    for (int sc = 0; sc < 4; sc++) {
        int c0 = sc*64;
        for (int j = tid; j < 1024; j += 256) {
            int hh = j >> 7, ss = (j >> 2) & 31, d4 = j & 3;
            // two s-rows per (hh,ss): ss and ss+32
            long gi0 = (((long)(nn*NH+hh))*SW + c0+ss)*DH + d4*4;
            long gi1 = (((long)(nn*NH+hh))*SW + c0+ss+32)*DH + d4*4;
            *(float4*)(&sK[ss*160 + hh*20 + d4*4])      = *(const float4*)(kb + gi0);
            *(float4*)(&sK[(ss+32)*160 + hh*20 + d4*4]) = *(const float4*)(kb + gi1);
            *(float4*)(&sV[ss*160 + hh*20 + d4*4])      = *(const float4*)(vb + gi0);
            *(float4*)(&sV[(ss+32)*160 + hh*20 + d4*4]) = *(const float4*)(vb + gi1);
        }
        __syncthreads();

        for (int q4 = 0; q4 < 4; q4++) {
            int s0 = c0 + q4*16;
            int ns = s0 + 16;
            float nbuf[16];
#pragma unroll
            for (int i = 0; i < 16; i++) {
                float v = 0.f;
                if (ns < 256) v = __ldcs(prev + pr_base + (long)(ns+i)*NH);
                nbuf[i] = v;
            }
#pragma unroll
            for (int s = 0; s < 16; s++) {
                const float4* kd = (const float4*)&sK[(q4*16+s)*160 + h*20];
                float4 k0 = kd[0], k1 = kd[1], k2 = kd[2], k3 = kd[3];
                // 4 parallel partials: short dependency chain
                float d0 = q[0]*k0.x;  d0 = fmaf(q[1],k0.y,d0);  d0 = fmaf(q[2],k0.z,d0);  d0 = fmaf(q[3],k0.w,d0);
                float d1 = q[4]*k1.x;  d1 = fmaf(q[5],k1.y,d1);  d1 = fmaf(q[6],k1.z,d1);  d1 = fmaf(q[7],k1.w,d1);
                float d2 = q[8]*k2.x;  d2 = fmaf(q[9],k2.y,d2);  d2 = fmaf(q[10],k2.z,d2); d2 = fmaf(q[11],k2.w,d2);
                float d3 = q[12]*k3.x; d3 = fmaf(q[13],k3.y,d3); d3 = fmaf(q[14],k3.z,d3); d3 = fmaf(q[15],k3.w,d3);
                float r = ((d0+d1) + (d2+d3)) + pbuf[s];
                __stcs(raw + pr_base + (long)(s0+s)*NH, r);
                float e = __expf(0.25f * r);
                z += e;
                const float4* vd = (const float4*)&sV[(q4*16+s)*160 + h*20];
                float4 v0 = vd[0], v1 = vd[1], v2 = vd[2], v3 = vd[3];
                acc[0]=fmaf(e,v0.x,acc[0]);  acc[1]=fmaf(e,v0.y,acc[1]);
                acc[2]=fmaf(e,v0.z,acc[2]);  acc[3]=fmaf(e,v0.w,acc[3]);
                acc[4]=fmaf(e,v1.x,acc[4]);  acc[5]=fmaf(e,v1.y,acc[5]);
                acc[6]=fmaf(e,v1.z,acc[6]);  acc[7]=fmaf(e,v1.w,acc[7]);
                acc[8]=fmaf(e,v2.x,acc[8]);  acc[9]=fmaf(e,v2.y,acc[9]);
                acc[10]=fmaf(e,v2.z,acc[10]); acc[11]=fmaf(e,v2.w,acc[11]);
                acc[12]=fmaf(e,v3.x,acc[12]); acc[13]=fmaf(e,v3.y,acc[13]);
                acc[14]=fmaf(e,v3.z,acc[14]); acc[15]=fmaf(e,v3.w,acc[15]);
            }
#pragma unroll
            for (int i = 0; i < 16; i++) pbuf[i] = nbuf[i];
        }
        __syncthreads();
    }
    float inv = 1.f / z;
    float* mp = g_msg[side] + ((long)(nn*SW + l))*C + h*DH;
#pragma unroll
    for (int i = 0; i < 4; i++)
        *(float4*)(mp + 4*i) = make_float4(acc[4*i]*inv, acc[4*i+1]*inv,
                                           acc[4*i+2]*inv, acc[4*i+3]*inv);
}

// ---------------------------------------------------------------------------
// Kernel 3: fused LN1 + FFN (tf32 mma.sync) + residual + LN2. 32 rows/block.
// ---------------------------------------------------------------------------
#define XPITCH 132
#define HPITCH 516

__global__ __launch_bounds__(256, 2) void ffn_kernel(
    const float* __restrict__ feat_l, const float* __restrict__ feat_r,
    const float* __restrict__ b1, const float* __restrict__ b2,
    const float* __restrict__ lg1, const float* __restrict__ lb1,
    const float* __restrict__ lg2, const float* __restrict__ lb2,
    float* __restrict__ d_out)
{
    extern __shared__ float smem[];
    float* sX = smem;                 // 32 x 132 fp32 (LN1 out / residual)
    float* sH = smem + 32*XPITCH;     // 32 x 516 (tf32-rounded gelu; then out tile)
    int tid  = threadIdx.x;
    int side = blockIdx.y;
    const float* feat = side ? feat_r : feat_l;
    const float* msg  = g_msg[side];
    float* outp = d_out + (side ? OUT_R : OUT_L);
    int row0 = blockIdx.x * 32;
    int warp = tid >> 5, lane = tid & 31;
    int gid = lane >> 2, tig = lane & 3;
    int mt = warp & 1, ng = warp >> 1;
    int m0 = mt*16;

    // load feat + msg
    for (int j = tid; j < 1024; j += 256) {
        int r = j >> 5, c4 = j & 31;
        long gi = ((long)(row0+r))*C + c4*4;
        float4 a = *(const float4*)(feat + gi);
        float4 b = *(const float4*)(msg + gi);
        a.x += b.x; a.y += b.y; a.z += b.z; a.w += b.w;
        *(float4*)(&sX[r*XPITCH + c4*4]) = a;
    }
    __syncthreads();

    // LN1 in place
#pragma unroll
    for (int rr = 0; rr < 4; rr++) {
        int r = warp*4 + rr;
        float v0 = sX[r*XPITCH+lane],    v1 = sX[r*XPITCH+lane+32];
        float v2 = sX[r*XPITCH+lane+64], v3 = sX[r*XPITCH+lane+96];
        float sum = v0+v1+v2+v3;
        float sq  = v0*v0+v1*v1+v2*v2+v3*v3;
        for (int o = 16; o; o >>= 1) {
            sum += __shfl_xor_sync(~0u, sum, o);
            sq  += __shfl_xor_sync(~0u, sq,  o);
        }
        float mu = sum*(1.f/128.f);
        float rs = rsqrtf(sq*(1.f/128.f) - mu*mu + 1e-5f);
        sX[r*XPITCH+lane]    = (v0-mu)*rs*lg1[lane]    + lb1[lane];
        sX[r*XPITCH+lane+32] = (v1-mu)*rs*lg1[lane+32] + lb1[lane+32];
        sX[r*XPITCH+lane+64] = (v2-mu)*rs*lg1[lane+64] + lb1[lane+64];
        sX[r*XPITCH+lane+96] = (v3-mu)*rs*lg1[lane+96] + lb1[lane+96];
    }
    __syncthreads();

    // GEMM1: H[32,512] = X @ W1.  warp: m16 tile mt, cols [ng*128, ng*128+128)
    {
        float acc[16][4];
#pragma unroll
        for (int t = 0; t < 16; t++)
#pragma unroll
            for (int j = 0; j < 4; j++) acc[t][j] = 0.f;

#pragma unroll 2
        for (int ks = 0; ks < 16; ks++) {
            int k0 = ks*8;
            unsigned a0 = f2tf32(sX[(m0+gid)*XPITCH   + k0 + tig]);
            unsigned a1 = f2tf32(sX[(m0+gid+8)*XPITCH + k0 + tig]);
            unsigned a2 = f2tf32(sX[(m0+gid)*XPITCH   + k0 + tig + 4]);
            unsigned a3 = f2tf32(sX[(m0+gid+8)*XPITCH + k0 + tig + 4]);
            const float4* bp = (const float4*)g_w1f + (ks*32 + ng*8)*32 + lane;
#pragma unroll
            for (int tp = 0; tp < 8; tp++) {
                float4 b = bp[tp*32];
                mma_tf32(acc[2*tp],   a0,a1,a2,a3, __float_as_uint(b.x), __float_as_uint(b.y));
                mma_tf32(acc[2*tp+1], a0,a1,a2,a3, __float_as_uint(b.z), __float_as_uint(b.w));
            }
        }
        // bias + gelu + tf32-round, store H
#pragma unroll
        for (int t = 0; t < 16; t++) {
            int col = ng*128 + t*8 + 2*tig;
            float h00 = acc[t][0] + b1[col];
            float h01 = acc[t][1] + b1[col+1];
            float h10 = acc[t][2] + b1[col];
            float h11 = acc[t][3] + b1[col+1];
            h00 = 0.5f*h00*(1.f + erff(h00*0.70710678118654752f));
            h01 = 0.5f*h01*(1.f + erff(h01*0.70710678118654752f));
            h10 = 0.5f*h10*(1.f + erff(h10*0.70710678118654752f));
            h11 = 0.5f*h11*(1.f + erff(h11*0.70710678118654752f));
            float2 lo = make_float2(__uint_as_float(f2tf32(h00)), __uint_as_float(f2tf32(h01)));
            float2 hi = make_float2(__uint_as_float(f2tf32(h10)), __uint_as_float(f2tf32(h11)));
            *(float2*)(&sH[(m0+gid)*HPITCH   + col]) = lo;
            *(float2*)(&sH[(m0+gid+8)*HPITCH + col]) = hi;
        }
    }
    __syncthreads();

    // GEMM2: O[32,128] = H @ W2.  warp: m16 tile mt, cols [ng*32, ng*32+32)
    float acc2[4][4];
#pragma unroll
    for (int t = 0; t < 4; t++)
#pragma unroll
        for (int j = 0; j < 4; j++) acc2[t][j] = 0.f;
    {
        const unsigned* sHi = (const unsigned*)sH;   // tf32 bit patterns
#pragma unroll 4
        for (int ks = 0; ks < 64; ks++) {
            int k0 = ks*8;
            unsigned a0 = sHi[(m0+gid)*HPITCH   + k0 + tig];
            unsigned a1 = sHi[(m0+gid+8)*HPITCH + k0 + tig];
            unsigned a2 = sHi[(m0+gid)*HPITCH   + k0 + tig + 4];
            unsigned a3 = sHi[(m0+gid+8)*HPITCH + k0 + tig + 4];
            const float4* bp = (const float4*)g_w2f + (ks*8 + ng*2)*32 + lane;
            float4 b0v = bp[0];
            float4 b1v = bp[32];
            mma_tf32(acc2[0], a0,a1,a2,a3, __float_as_uint(b0v.x), __float_as_uint(b0v.y));
            mma_tf32(acc2[1], a0,a1,a2,a3, __float_as_uint(b0v.z), __float_as_uint(b0v.w));
            mma_tf32(acc2[2], a0,a1,a2,a3, __float_as_uint(b1v.x), __float_as_uint(b1v.y));
            mma_tf32(acc2[3], a0,a1,a2,a3, __float_as_uint(b1v.z), __float_as_uint(b1v.w));
        }
    }
    __syncthreads();   // all reads of sH done; reuse as out tile (pitch XPITCH)

    // residual + bias, store out tile
#pragma unroll
    for (int t = 0; t < 4; t++) {
        int col = ng*32 + t*8 + 2*tig;
        int r0 = m0+gid, r1 = m0+gid+8;
        float2 lo, hi;
        lo.x = acc2[t][0] + b2[col]   + sX[r0*XPITCH + col];
        lo.y = acc2[t][1] + b2[col+1] + sX[r0*XPITCH + col + 1];
        hi.x = acc2[t][2] + b2[col]   + sX[r1*XPITCH + col];
        hi.y = acc2[t][3] + b2[col+1] + sX[r1*XPITCH + col + 1];
        *(float2*)(&sH[r0*XPITCH + col]) = lo;
        *(float2*)(&sH[r1*XPITCH + col]) = hi;
    }
    __syncthreads();

    // LN2 + write out
#pragma unroll
    for (int rr = 0; rr < 4; rr++) {
        int r = warp*4 + rr;
        float v0 = sH[r*XPITCH+lane],    v1 = sH[r*XPITCH+lane+32];
        float v2 = sH[r*XPITCH+lane+64], v3 = sH[r*XPITCH+lane+96];
        float sum = v0+v1+v2+v3;
        float sq  = v0*v0+v1*v1+v2*v2+v3*v3;
        for (int o = 16; o; o >>= 1) {
            sum += __shfl_xor_sync(~0u, sum, o);
            sq  += __shfl_xor_sync(~0u, sq,  o);
        }
        float mu = sum*(1.f/128.f);
        float rs = rsqrtf(sq*(1.f/128.f) - mu*mu + 1e-5f);
        long go = ((long)(row0+r))*C;
        outp[go+lane]    = (v0-mu)*rs*lg2[lane]    + lb2[lane];
        outp[go+lane+32] = (v1-mu)*rs*lg2[lane+32] + lb2[lane+32];
        outp[go+lane+64] = (v2-mu)*rs*lg2[lane+64] + lb2[lane+64];
        outp[go+lane+96] = (v3-mu)*rs*lg2[lane+96] + lb2[lane+96];
    }
}

// ---------------------------------------------------------------------------
extern "C" void kernel_launch(void* const* d_in, const int* in_sizes, int n_in,
                              void* d_out, int out_size)
{
    const float* feat_l = (const float*)d_in[0];
    const float* feat_r = (const float*)d_in[1];
    const float* prev_l = (const float*)d_in[2];
    const float* prev_r = (const float*)d_in[3];
    const float* kqv_w  = (const float*)d_in[4];
    const float* ff_w1  = (const float*)d_in[5];
    const float* ff_b1  = (const float*)d_in[6];
    const float* ff_w2  = (const float*)d_in[7];
    const float* ff_b2  = (const float*)d_in[8];
    const float* ln1_g  = (const float*)d_in[9];
    const float* ln1_b  = (const float*)d_in[10];
    const float* ln2_g  = (const float*)d_in[11];
    const float* ln2_b  = (const float*)d_in[12];
    float* out = (float*)d_out;

    const int FFN_SMEM = (32*XPITCH + 32*HPITCH) * 4;   // 82944 B
    cudaFuncSetAttribute(ffn_kernel, cudaFuncAttributeMaxDynamicSharedMemorySize, FFN_SMEM);

    prep_kernel<<<128, 256>>>(ff_w1, ff_w2);
    proj_kernel<<<dim3(NTOK/32, 2), 256>>>(feat_l, feat_r, kqv_w);
    attn_kernel<<<dim3(SW/32, NSEQ, 2), 256>>>(prev_l, prev_r, out);
    ffn_kernel<<<dim3(NTOK/32, 2), 256, FFN_SMEM>>>(
        feat_l, feat_r, ff_b1, ff_b2,
        ln1_g, ln1_b, ln2_g, ln2_b, out);
}

// round 7
// speedup vs baseline: 3.4868x; 1.4847x over previous
#include <cuda_runtime.h>
#include <math.h>

#define NSEQ 80
#define SW 256
#define C 128
#define NH 8
#define DH 16
#define FF 512
#define NTOK (NSEQ*SW)          // 20480
#define TOKC (NTOK*C)           // 2621440

#define OUT_L 0
#define OUT_R TOKC
#define RAW_L (2*TOKC)
#define RAW_R (2*TOKC + NSEQ*SW*SW*NH)

// Scratch (device globals: allocation-free)
__device__ float g_k[2][TOKC];
__device__ float g_q[2][TOKC];
__device__ float g_v[2][TOKC];
__device__ float g_msg[2][TOKC];
__device__ float g_w1f[16*32*32*4];   // W1 tf32 frag layout
__device__ float g_w2f[64*8*32*4];    // W2 tf32 frag layout

// ---- tf32 mma helpers ----
__device__ __forceinline__ unsigned f2tf32(float x) {
    unsigned r; asm("cvt.rna.tf32.f32 %0, %1;" : "=r"(r) : "f"(x)); return r;
}
__device__ __forceinline__ void mma_tf32(float* c,
    unsigned a0, unsigned a1, unsigned a2, unsigned a3,
    unsigned b0, unsigned b1)
{
    asm("mma.sync.aligned.m16n8k8.row.col.f32.tf32.tf32.f32 "
        "{%0,%1,%2,%3},{%4,%5,%6,%7},{%8,%9},{%0,%1,%2,%3};"
        : "+f"(c[0]), "+f"(c[1]), "+f"(c[2]), "+f"(c[3])
        : "r"(a0), "r"(a1), "r"(a2), "r"(a3), "r"(b0), "r"(b1));
}

// ---------------------------------------------------------------------------
// Kernel 0: W1/W2 -> tf32 fragment layouts.
// ---------------------------------------------------------------------------
__global__ __launch_bounds__(256) void prep_kernel(
    const float* __restrict__ w1, const float* __restrict__ w2)
{
    int i = blockIdx.x * 256 + threadIdx.x;     // 0..32767
    if (i < 16384) {
        int lane = i & 31, tp = (i >> 5) & 31, ks = i >> 10;
        int gid = lane >> 2, tig = lane & 3;
        int k0 = ks*8, n0 = (2*tp)*8, n1 = (2*tp+1)*8;
        float4 o;
        o.x = __uint_as_float(f2tf32(w1[(k0+tig)*FF   + n0+gid]));
        o.y = __uint_as_float(f2tf32(w1[(k0+tig+4)*FF + n0+gid]));
        o.z = __uint_as_float(f2tf32(w1[(k0+tig)*FF   + n1+gid]));
        o.w = __uint_as_float(f2tf32(w1[(k0+tig+4)*FF + n1+gid]));
        ((float4*)g_w1f)[i] = o;
    } else {
        int j = i - 16384;
        int lane = j & 31, tp = (j >> 5) & 7, ks = j >> 8;
        int gid = lane >> 2, tig = lane & 3;
        int k0 = ks*8, n0 = (2*tp)*8, n1 = (2*tp+1)*8;
        float4 o;
        o.x = __uint_as_float(f2tf32(w2[(k0+tig)*C   + n0+gid]));
        o.y = __uint_as_float(f2tf32(w2[(k0+tig+4)*C + n0+gid]));
        o.z = __uint_as_float(f2tf32(w2[(k0+tig)*C   + n1+gid]));
        o.w = __uint_as_float(f2tf32(w2[(k0+tig+4)*C + n1+gid]));
        ((float4*)g_w2f)[j] = o;
    }
}

// ---------------------------------------------------------------------------
// Kernel 1: per-head KQV projection with coalesced smem-staged stores.
// ---------------------------------------------------------------------------
__global__ __launch_bounds__(256) void proj_kernel(
    const float* __restrict__ feat_l, const float* __restrict__ feat_r,
    const float* __restrict__ kqv_w)
{
    __shared__ float sW[16*48];
    __shared__ float sO[8*548];
    int tid = threadIdx.x;
    for (int i = tid; i < 16*48; i += 256) sW[i] = kqv_w[i];

    int side = blockIdx.y;
    const float* feat = side ? feat_r : feat_l;
    int rl = tid >> 3;
    int h  = tid & 7;
    int row = blockIdx.x * 32 + rl;
    __syncthreads();

    float x[16];
    const float4* xp = (const float4*)(feat + (long)row*C + h*DH);
#pragma unroll
    for (int i = 0; i < 4; i++) {
        float4 t = xp[i];
        x[4*i+0]=t.x; x[4*i+1]=t.y; x[4*i+2]=t.z; x[4*i+3]=t.w;
    }
    float o[48];
#pragma unroll
    for (int j = 0; j < 48; j++) o[j] = 0.f;
#pragma unroll
    for (int i = 0; i < 16; i++) {
        float xi = x[i];
#pragma unroll
        for (int j = 0; j < 48; j++) o[j] = fmaf(xi, sW[i*48+j], o[j]);
    }

    int nn = row >> 8;
    int s0 = (blockIdx.x * 32) & 255;
    float* gdst[3] = { g_k[side], g_q[side], g_v[side] };

#pragma unroll
    for (int a = 0; a < 3; a++) {
        __syncthreads();
#pragma unroll
        for (int d = 0; d < 16; d++) sO[h*548 + rl*17 + d] = o[a*16 + d];
        __syncthreads();
        float* gp = gdst[a] + (((long)(nn*NH))*SW + s0) * DH;
        for (int j = tid; j < 4096; j += 256) {
            int hh = j >> 9, rem = j & 511, ss = rem >> 4, d = rem & 15;
            gp[(long)hh*SW*DH + ss*DH + d] = sO[hh*548 + ss*17 + d];
        }
    }
}

// ---------------------------------------------------------------------------
// Kernel 2: cross attention via tf32 mma. block = (lt, n, side), 8 warps = 8 h.
// QK: 3xTF32 error-split (fp32-grade raw). AV: plain tf32.
// prev/raw staged through smem per 32-s chunk; e->A-frag via quad shuffles.
// ---------------------------------------------------------------------------
#define PL 268    // sP pitch per l:  l*268 + h*33 + s
#define PK 172    // sK pitch per s:  s*172 + h*20 + d
#define PV 168    // sV pitch per s:  s*168 + h*20 + d
#define ATTN_SMEM ((32*PL + 32*PK + 32*PV)*4)   // 77824 B

__global__ __launch_bounds__(256, 2) void attn_kernel(
    const float* __restrict__ prev_l, const float* __restrict__ prev_r,
    float* __restrict__ d_out)
{
    extern __shared__ float sm[];
    float* sP = sm;                  // 32*268
    float* sK = sm + 32*PL;          // 32*172
    float* sV = sm + 32*PL + 32*PK;  // 32*168

    int tid = threadIdx.x;
    int lane = tid & 31;
    int h = tid >> 5;                // warp = head
    int gid = lane >> 2, tig = lane & 3;
    int lt = blockIdx.x, nn = blockIdx.y, side = blockIdx.z;
    int l0 = lt * 32;

    const float* prev = side ? prev_r : prev_l;
    float* raw = d_out + (side ? RAW_R : RAW_L);
    const float* qb = g_q[side];
    const float* kb = g_k[side ^ 1];
    const float* vb = g_v[side ^ 1];

    // ---- Q a-frags (held all kernel): [mt][kt] rows m0+gid/m0+gid+8, cols k0+tig/k0+tig+4
    unsigned qhi[2][2][4], qlo[2][2][4];
    {
        const float* qbase = qb + (((long)(nn*NH + h))*SW + l0)*DH;
#pragma unroll
        for (int mt = 0; mt < 2; mt++) {
#pragma unroll
            for (int kt = 0; kt < 2; kt++) {
                int r0 = mt*16 + gid, c0 = kt*8 + tig;
                float v0 = qbase[r0*DH + c0];
                float v1 = qbase[(r0+8)*DH + c0];
                float v2 = qbase[r0*DH + c0+4];
                float v3 = qbase[(r0+8)*DH + c0+4];
                qhi[mt][kt][0] = f2tf32(v0); qlo[mt][kt][0] = f2tf32(v0 - __uint_as_float(qhi[mt][kt][0]));
                qhi[mt][kt][1] = f2tf32(v1); qlo[mt][kt][1] = f2tf32(v1 - __uint_as_float(qhi[mt][kt][1]));
                qhi[mt][kt][2] = f2tf32(v2); qlo[mt][kt][2] = f2tf32(v2 - __uint_as_float(qhi[mt][kt][2]));
                qhi[mt][kt][3] = f2tf32(v3); qlo[mt][kt][3] = f2tf32(v3 - __uint_as_float(qhi[mt][kt][3]));
            }
        }
    }

    float z00 = 0.f, z01 = 0.f, z10 = 0.f, z11 = 0.f;   // z[mt][row0/row1]
    float acc[2][2][4];
#pragma unroll
    for (int mt = 0; mt < 2; mt++)
#pragma unroll
        for (int nt = 0; nt < 2; nt++)
#pragma unroll
            for (int j = 0; j < 4; j++) acc[mt][nt][j] = 0.f;

    for (int ch = 0; ch < 8; ch++) {
        int s0 = ch * 32;
        __syncthreads();   // prior raw-out + frag reads done before restage

        // ---- stage prev chunk [32l][32s][8h] -> sP[l][h][s]
#pragma unroll
        for (int i = 0; i < 8; i++) {
            int f = i*256 + tid;
            int l = f >> 6, rem = f & 63;
            int s = rem >> 1, hb = (rem & 1) * 4;
            float4 pv = *(const float4*)(prev + (((long)(nn*SW + l0+l))*SW + s0+s)*NH + hb);
            float* dp = sP + l*PL + hb*33 + s;
            dp[0] = pv.x; dp[33] = pv.y; dp[66] = pv.z; dp[99] = pv.w;
        }
        // ---- stage K, V chunks [8h][32s][16d] -> sK/sV [s][h][d]
#pragma unroll
        for (int i = 0; i < 4; i++) {
            int f = i*256 + tid;
            int hh = f >> 7, rem = f & 127;
            int s = rem >> 2, dq = rem & 3;
            long src = (((long)(nn*NH + hh))*SW + s0 + s)*DH + dq*4;
            *(float4*)(sK + s*PK + hh*20 + dq*4) = *(const float4*)(kb + src);
            *(float4*)(sV + s*PV + hh*20 + dq*4) = *(const float4*)(vb + src);
        }
        __syncthreads();

        // ---- QK mma: scores c[mt][st][4] for 32l x 32s (this head)
        float c[2][4][4];
#pragma unroll
        for (int mt = 0; mt < 2; mt++)
#pragma unroll
            for (int st = 0; st < 4; st++)
#pragma unroll
                for (int j = 0; j < 4; j++) c[mt][st][j] = 0.f;

#pragma unroll
        for (int st = 0; st < 4; st++) {
            const float* kr = sK + (st*8 + gid)*PK + h*20;
            float kv0 = kr[tig], kv1 = kr[tig+4], kv2 = kr[tig+8], kv3 = kr[tig+12];
            unsigned kh0 = f2tf32(kv0), kh1 = f2tf32(kv1), kh2 = f2tf32(kv2), kh3 = f2tf32(kv3);
            unsigned kl0 = f2tf32(kv0 - __uint_as_float(kh0));
            unsigned kl1 = f2tf32(kv1 - __uint_as_float(kh1));
            unsigned kl2 = f2tf32(kv2 - __uint_as_float(kh2));
            unsigned kl3 = f2tf32(kv3 - __uint_as_float(kh3));
#pragma unroll
            for (int mt = 0; mt < 2; mt++) {
                mma_tf32(c[mt][st], qhi[mt][0][0], qhi[mt][0][1], qhi[mt][0][2], qhi[mt][0][3], kh0, kh1);
                mma_tf32(c[mt][st], qhi[mt][0][0], qhi[mt][0][1], qhi[mt][0][2], qhi[mt][0][3], kl0, kl1);
                mma_tf32(c[mt][st], qlo[mt][0][0], qlo[mt][0][1], qlo[mt][0][2], qlo[mt][0][3], kh0, kh1);
                mma_tf32(c[mt][st], qhi[mt][1][0], qhi[mt][1][1], qhi[mt][1][2], qhi[mt][1][3], kh2, kh3);
                mma_tf32(c[mt][st], qhi[mt][1][0], qhi[mt][1][1], qhi[mt][1][2], qhi[mt][1][3], kl2, kl3);
                mma_tf32(c[mt][st], qlo[mt][1][0], qlo[mt][1][1], qlo[mt][1][2], qlo[mt][1][3], kh2, kh3);
            }
        }

        // ---- prev add, raw write (to sP in place), exp, z; e replaces c
#pragma unroll
        for (int mt = 0; mt < 2; mt++) {
#pragma unroll
            for (int st = 0; st < 4; st++) {
                float* pp = sP + (mt*16 + gid)*PL + h*33 + st*8 + 2*tig;
                float r0 = c[mt][st][0] + pp[0];
                float r1 = c[mt][st][1] + pp[1];
                float r2 = c[mt][st][2] + pp[8*PL];
                float r3 = c[mt][st][3] + pp[8*PL + 1];
                pp[0] = r0; pp[1] = r1; pp[8*PL] = r2; pp[8*PL + 1] = r3;
                float e0 = __expf(0.25f*r0), e1 = __expf(0.25f*r1);
                float e2 = __expf(0.25f*r2), e3 = __expf(0.25f*r3);
                if (mt == 0) { z00 += e0 + e1; z01 += e2 + e3; }
                else         { z10 += e0 + e1; z11 += e2 + e3; }
                c[mt][st][0] = e0; c[mt][st][1] = e1; c[mt][st][2] = e2; c[mt][st][3] = e3;
            }
        }

        // ---- AV mma: acc[mt][nt] += E(m16 x k8=st) * V(k8 x n8)
        int srcA = (lane & 28) | (tig >> 1);
        int srcB = srcA + 2;
        bool odd = (tig & 1);
#pragma unroll
        for (int st = 0; st < 4; st++) {
            unsigned a[2][4];
#pragma unroll
            for (int mt = 0; mt < 2; mt++) {
                float e0 = c[mt][st][0], e1 = c[mt][st][1];
                float e2 = c[mt][st][2], e3 = c[mt][st][3];
                float g00 = __shfl_sync(0xffffffffu, e0, srcA);
                float g01 = __shfl_sync(0xffffffffu, e1, srcA);
                float g20 = __shfl_sync(0xffffffffu, e2, srcA);
                float g21 = __shfl_sync(0xffffffffu, e3, srcA);
                float h00 = __shfl_sync(0xffffffffu, e0, srcB);
                float h01 = __shfl_sync(0xffffffffu, e1, srcB);
                float h20 = __shfl_sync(0xffffffffu, e2, srcB);
                float h21 = __shfl_sync(0xffffffffu, e3, srcB);
                a[mt][0] = f2tf32(odd ? g01 : g00);
                a[mt][1] = f2tf32(odd ? g21 : g20);
                a[mt][2] = f2tf32(odd ? h01 : h00);
                a[mt][3] = f2tf32(odd ? h21 : h20);
            }
            const float* vr0 = sV + (st*8 + tig)*PV + h*20;
            const float* vr1 = sV + (st*8 + tig + 4)*PV + h*20;
#pragma unroll
            for (int nt = 0; nt < 2; nt++) {
                unsigned vb0 = f2tf32(vr0[nt*8 + gid]);
                unsigned vb1 = f2tf32(vr1[nt*8 + gid]);
                mma_tf32(acc[0][nt], a[0][0], a[0][1], a[0][2], a[0][3], vb0, vb1);
                mma_tf32(acc[1][nt], a[1][0], a[1][1], a[1][2], a[1][3], vb0, vb1);
            }
        }

        // ---- raw out: sP -> gmem (coalesced)
        __syncthreads();
#pragma unroll
        for (int i = 0; i < 8; i++) {
            int f = i*256 + tid;
            int l = f >> 6, rem = f & 63;
            int s = rem >> 1, hb = (rem & 1) * 4;
            float* dp = sP + l*PL + hb*33 + s;
            float4 rv = make_float4(dp[0], dp[33], dp[66], dp[99]);
            *(float4*)(raw + (((long)(nn*SW + l0+l))*SW + s0+s)*NH + hb) = rv;
        }
    }

    // ---- z quad-reduce (cols split across tig lanes)
    z00 += __shfl_xor_sync(0xffffffffu, z00, 1); z00 += __shfl_xor_sync(0xffffffffu, z00, 2);
    z01 += __shfl_xor_sync(0xffffffffu, z01, 1); z01 += __shfl_xor_sync(0xffffffffu, z01, 2);
    z10 += __shfl_xor_sync(0xffffffffu, z10, 1); z10 += __shfl_xor_sync(0xffffffffu, z10, 2);
    z11 += __shfl_xor_sync(0xffffffffu, z11, 1); z11 += __shfl_xor_sync(0xffffffffu, z11, 2);
    float iz[2][2] = { {1.f/z00, 1.f/z01}, {1.f/z10, 1.f/z11} };

    // ---- msg out
    float* mb = g_msg[side];
#pragma unroll
    for (int mt = 0; mt < 2; mt++) {
#pragma unroll
        for (int nt = 0; nt < 2; nt++) {
            long base = ((long)(nn*SW + l0 + mt*16 + gid))*C + h*DH + nt*8 + 2*tig;
            *(float2*)(mb + base)       = make_float2(acc[mt][nt][0]*iz[mt][0], acc[mt][nt][1]*iz[mt][0]);
            *(float2*)(mb + base + 8*C) = make_float2(acc[mt][nt][2]*iz[mt][1], acc[mt][nt][3]*iz[mt][1]);
        }
    }
}

// ---------------------------------------------------------------------------
// Kernel 3: fused LN1 + FFN (tf32 mma.sync) + residual + LN2. 32 rows/block.
// ---------------------------------------------------------------------------
#define XPITCH 132
#define HPITCH 516

__global__ __launch_bounds__(256, 2) void ffn_kernel(
    const float* __restrict__ feat_l, const float* __restrict__ feat_r,
    const float* __restrict__ b1, const float* __restrict__ b2,
    const float* __restrict__ lg1, const float* __restrict__ lb1,
    const float* __restrict__ lg2, const float* __restrict__ lb2,
    float* __restrict__ d_out)
{
    extern __shared__ float smem[];
    float* sX = smem;
    float* sH = smem + 32*XPITCH;
    int tid  = threadIdx.x;
    int side = blockIdx.y;
    const float* feat = side ? feat_r : feat_l;
    const float* msg  = g_msg[side];
    float* outp = d_out + (side ? OUT_R : OUT_L);
    int row0 = blockIdx.x * 32;
    int warp = tid >> 5, lane = tid & 31;
    int gid = lane >> 2, tig = lane & 3;
    int mt = warp & 1, ng = warp >> 1;
    int m0 = mt*16;

    for (int j = tid; j < 1024; j += 256) {
        int r = j >> 5, c4 = j & 31;
        long gi = ((long)(row0+r))*C + c4*4;
        float4 a = *(const float4*)(feat + gi);
        float4 b = *(const float4*)(msg + gi);
        a.x += b.x; a.y += b.y; a.z += b.z; a.w += b.w;
        *(float4*)(&sX[r*XPITCH + c4*4]) = a;
    }
    __syncthreads();

#pragma unroll
    for (int rr = 0; rr < 4; rr++) {
        int r = warp*4 + rr;
        float v0 = sX[r*XPITCH+lane],    v1 = sX[r*XPITCH+lane+32];
        float v2 = sX[r*XPITCH+lane+64], v3 = sX[r*XPITCH+lane+96];
        float sum = v0+v1+v2+v3;
        float sq  = v0*v0+v1*v1+v2*v2+v3*v3;
        for (int o = 16; o; o >>= 1) {
            sum += __shfl_xor_sync(~0u, sum, o);
            sq  += __shfl_xor_sync(~0u, sq,  o);
        }
        float mu = sum*(1.f/128.f);
        float rs = rsqrtf(sq*(1.f/128.f) - mu*mu + 1e-5f);
        sX[r*XPITCH+lane]    = (v0-mu)*rs*lg1[lane]    + lb1[lane];
        sX[r*XPITCH+lane+32] = (v1-mu)*rs*lg1[lane+32] + lb1[lane+32];
        sX[r*XPITCH+lane+64] = (v2-mu)*rs*lg1[lane+64] + lb1[lane+64];
        sX[r*XPITCH+lane+96] = (v3-mu)*rs*lg1[lane+96] + lb1[lane+96];
    }
    __syncthreads();

    {
        float acc[16][4];
#pragma unroll
        for (int t = 0; t < 16; t++)
#pragma unroll
            for (int j = 0; j < 4; j++) acc[t][j] = 0.f;

#pragma unroll 2
        for (int ks = 0; ks < 16; ks++) {
            int k0 = ks*8;
            unsigned a0 = f2tf32(sX[(m0+gid)*XPITCH   + k0 + tig]);
            unsigned a1 = f2tf32(sX[(m0+gid+8)*XPITCH + k0 + tig]);
            unsigned a2 = f2tf32(sX[(m0+gid)*XPITCH   + k0 + tig + 4]);
            unsigned a3 = f2tf32(sX[(m0+gid+8)*XPITCH + k0 + tig + 4]);
            const float4* bp = (const float4*)g_w1f + (ks*32 + ng*8)*32 + lane;
#pragma unroll
            for (int tp = 0; tp < 8; tp++) {
                float4 b = bp[tp*32];
                mma_tf32(acc[2*tp],   a0,a1,a2,a3, __float_as_uint(b.x), __float_as_uint(b.y));
                mma_tf32(acc[2*tp+1], a0,a1,a2,a3, __float_as_uint(b.z), __float_as_uint(b.w));
            }
        }
#pragma unroll
        for (int t = 0; t < 16; t++) {
            int col = ng*128 + t*8 + 2*tig;
            float h00 = acc[t][0] + b1[col];
            float h01 = acc[t][1] + b1[col+1];
            float h10 = acc[t][2] + b1[col];
            float h11 = acc[t][3] + b1[col+1];
            h00 = 0.5f*h00*(1.f + erff(h00*0.70710678118654752f));
            h01 = 0.5f*h01*(1.f + erff(h01*0.70710678118654752f));
            h10 = 0.5f*h10*(1.f + erff(h10*0.70710678118654752f));
            h11 = 0.5f*h11*(1.f + erff(h11*0.70710678118654752f));
            float2 lo = make_float2(__uint_as_float(f2tf32(h00)), __uint_as_float(f2tf32(h01)));
            float2 hi = make_float2(__uint_as_float(f2tf32(h10)), __uint_as_float(f2tf32(h11)));
            *(float2*)(&sH[(m0+gid)*HPITCH   + col]) = lo;
            *(float2*)(&sH[(m0+gid+8)*HPITCH + col]) = hi;
        }
    }
    __syncthreads();

    float acc2[4][4];
#pragma unroll
    for (int t = 0; t < 4; t++)
#pragma unroll
        for (int j = 0; j < 4; j++) acc2[t][j] = 0.f;
    {
        const unsigned* sHi = (const unsigned*)sH;
#pragma unroll 4
        for (int ks = 0; ks < 64; ks++) {
            int k0 = ks*8;
            unsigned a0 = sHi[(m0+gid)*HPITCH   + k0 + tig];
            unsigned a1 = sHi[(m0+gid+8)*HPITCH + k0 + tig];
            unsigned a2 = sHi[(m0+gid)*HPITCH   + k0 + tig + 4];
            unsigned a3 = sHi[(m0+gid+8)*HPITCH + k0 + tig + 4];
            const float4* bp = (const float4*)g_w2f + (ks*8 + ng*2)*32 + lane;
            float4 b0v = bp[0];
            float4 b1v = bp[32];
            mma_tf32(acc2[0], a0,a1,a2,a3, __float_as_uint(b0v.x), __float_as_uint(b0v.y));
            mma_tf32(acc2[1], a0,a1,a2,a3, __float_as_uint(b0v.z), __float_as_uint(b0v.w));
            mma_tf32(acc2[2], a0,a1,a2,a3, __float_as_uint(b1v.x), __float_as_uint(b1v.y));
            mma_tf32(acc2[3], a0,a1,a2,a3, __float_as_uint(b1v.z), __float_as_uint(b1v.w));
        }
    }
    __syncthreads();

#pragma unroll
    for (int t = 0; t < 4; t++) {
        int col = ng*32 + t*8 + 2*tig;
        int r0 = m0+gid, r1 = m0+gid+8;
        float2 lo, hi;
        lo.x = acc2[t][0] + b2[col]   + sX[r0*XPITCH + col];
        lo.y = acc2[t][1] + b2[col+1] + sX[r0*XPITCH + col + 1];
        hi.x = acc2[t][2] + b2[col]   + sX[r1*XPITCH + col];
        hi.y = acc2[t][3] + b2[col+1] + sX[r1*XPITCH + col + 1];
        *(float2*)(&sH[r0*XPITCH + col]) = lo;
        *(float2*)(&sH[r1*XPITCH + col]) = hi;
    }
    __syncthreads();

#pragma unroll
    for (int rr = 0; rr < 4; rr++) {
        int r = warp*4 + rr;
        float v0 = sH[r*XPITCH+lane],    v1 = sH[r*XPITCH+lane+32];
        float v2 = sH[r*XPITCH+lane+64], v3 = sH[r*XPITCH+lane+96];
        float sum = v0+v1+v2+v3;
        float sq  = v0*v0+v1*v1+v2*v2+v3*v3;
        for (int o = 16; o; o >>= 1) {
            sum += __shfl_xor_sync(~0u, sum, o);
            sq  += __shfl_xor_sync(~0u, sq,  o);
        }
        float mu = sum*(1.f/128.f);
        float rs = rsqrtf(sq*(1.f/128.f) - mu*mu + 1e-5f);
        long go = ((long)(row0+r))*C;
        outp[go+lane]    = (v0-mu)*rs*lg2[lane]    + lb2[lane];
        outp[go+lane+32] = (v1-mu)*rs*lg2[lane+32] + lb2[lane+32];
        outp[go+lane+64] = (v2-mu)*rs*lg2[lane+64] + lb2[lane+64];
        outp[go+lane+96] = (v3-mu)*rs*lg2[lane+96] + lb2[lane+96];
    }
}

// ---------------------------------------------------------------------------
extern "C" void kernel_launch(void* const* d_in, const int* in_sizes, int n_in,
                              void* d_out, int out_size)
{
    const float* feat_l = (const float*)d_in[0];
    const float* feat_r = (const float*)d_in[1];
    const float* prev_l = (const float*)d_in[2];
    const float* prev_r = (const float*)d_in[3];
    const float* kqv_w  = (const float*)d_in[4];
    const float* ff_w1  = (const float*)d_in[5];
    const float* ff_b1  = (const float*)d_in[6];
    const float* ff_w2  = (const float*)d_in[7];
    const float* ff_b2  = (const float*)d_in[8];
    const float* ln1_g  = (const float*)d_in[9];
    const float* ln1_b  = (const float*)d_in[10];
    const float* ln2_g  = (const float*)d_in[11];
    const float* ln2_b  = (const float*)d_in[12];
    float* out = (float*)d_out;

    const int FFN_SMEM = (32*XPITCH + 32*HPITCH) * 4;   // 82944 B
    cudaFuncSetAttribute(ffn_kernel, cudaFuncAttributeMaxDynamicSharedMemorySize, FFN_SMEM);
    cudaFuncSetAttribute(attn_kernel, cudaFuncAttributeMaxDynamicSharedMemorySize, ATTN_SMEM);

    prep_kernel<<<128, 256>>>(ff_w1, ff_w2);
    proj_kernel<<<dim3(NTOK/32, 2), 256>>>(feat_l, feat_r, kqv_w);
    attn_kernel<<<dim3(SW/32, NSEQ, 2), 256, ATTN_SMEM>>>(prev_l, prev_r, out);
    ffn_kernel<<<dim3(NTOK/32, 2), 256, FFN_SMEM>>>(
        feat_l, feat_r, ff_b1, ff_b2,
        ln1_g, ln1_b, ln2_g, ln2_b, out);
}

// round 8
// speedup vs baseline: 3.5244x; 1.0108x over previous
#include <cuda_runtime.h>
#include <math.h>

#define NSEQ 80
#define SW 256
#define C 128
#define NH 8
#define DH 16
#define FF 512
#define NTOK (NSEQ*SW)          // 20480
#define TOKC (NTOK*C)           // 2621440

#define OUT_L 0
#define OUT_R TOKC
#define RAW_L (2*TOKC)
#define RAW_R (2*TOKC + NSEQ*SW*SW*NH)

// Scratch (device globals: allocation-free)
__device__ float g_k[2][TOKC];
__device__ float g_q[2][TOKC];
__device__ float g_v[2][TOKC];
__device__ float g_msg[2][TOKC];
__device__ float g_w1f[16*32*32*4];   // W1 tf32 frag layout
__device__ float g_w2f[64*8*32*4];    // W2 tf32 frag layout

// ---- tf32 mma helpers ----
__device__ __forceinline__ unsigned f2tf32(float x) {
    unsigned r; asm("cvt.rna.tf32.f32 %0, %1;" : "=r"(r) : "f"(x)); return r;
}
__device__ __forceinline__ void mma_tf32(float* c,
    unsigned a0, unsigned a1, unsigned a2, unsigned a3,
    unsigned b0, unsigned b1)
{
    asm("mma.sync.aligned.m16n8k8.row.col.f32.tf32.tf32.f32 "
        "{%0,%1,%2,%3},{%4,%5,%6,%7},{%8,%9},{%0,%1,%2,%3};"
        : "+f"(c[0]), "+f"(c[1]), "+f"(c[2]), "+f"(c[3])
        : "r"(a0), "r"(a1), "r"(a2), "r"(a3), "r"(b0), "r"(b1));
}

// ---------------------------------------------------------------------------
// Kernel 0: W1/W2 -> tf32 fragment layouts.
// ---------------------------------------------------------------------------
__global__ __launch_bounds__(256) void prep_kernel(
    const float* __restrict__ w1, const float* __restrict__ w2)
{
    int i = blockIdx.x * 256 + threadIdx.x;     // 0..32767
    if (i < 16384) {
        int lane = i & 31, tp = (i >> 5) & 31, ks = i >> 10;
        int gid = lane >> 2, tig = lane & 3;
        int k0 = ks*8, n0 = (2*tp)*8, n1 = (2*tp+1)*8;
        float4 o;
        o.x = __uint_as_float(f2tf32(w1[(k0+tig)*FF   + n0+gid]));
        o.y = __uint_as_float(f2tf32(w1[(k0+tig+4)*FF + n0+gid]));
        o.z = __uint_as_float(f2tf32(w1[(k0+tig)*FF   + n1+gid]));
        o.w = __uint_as_float(f2tf32(w1[(k0+tig+4)*FF + n1+gid]));
        ((float4*)g_w1f)[i] = o;
    } else {
        int j = i - 16384;
        int lane = j & 31, tp = (j >> 5) & 7, ks = j >> 8;
        int gid = lane >> 2, tig = lane & 3;
        int k0 = ks*8, n0 = (2*tp)*8, n1 = (2*tp+1)*8;
        float4 o;
        o.x = __uint_as_float(f2tf32(w2[(k0+tig)*C   + n0+gid]));
        o.y = __uint_as_float(f2tf32(w2[(k0+tig+4)*C + n0+gid]));
        o.z = __uint_as_float(f2tf32(w2[(k0+tig)*C   + n1+gid]));
        o.w = __uint_as_float(f2tf32(w2[(k0+tig+4)*C + n1+gid]));
        ((float4*)g_w2f)[j] = o;
    }
}

// ---------------------------------------------------------------------------
// Kernel 1: per-head KQV projection with coalesced smem-staged stores.
// ---------------------------------------------------------------------------
__global__ __launch_bounds__(256) void proj_kernel(
    const float* __restrict__ feat_l, const float* __restrict__ feat_r,
    const float* __restrict__ kqv_w)
{
    __shared__ float sW[16*48];
    __shared__ float sO[8*548];
    int tid = threadIdx.x;
    for (int i = tid; i < 16*48; i += 256) sW[i] = kqv_w[i];

    int side = blockIdx.y;
    const float* feat = side ? feat_r : feat_l;
    int rl = tid >> 3;
    int h  = tid & 7;
    int row = blockIdx.x * 32 + rl;
    __syncthreads();

    float x[16];
    const float4* xp = (const float4*)(feat + (long)row*C + h*DH);
#pragma unroll
    for (int i = 0; i < 4; i++) {
        float4 t = xp[i];
        x[4*i+0]=t.x; x[4*i+1]=t.y; x[4*i+2]=t.z; x[4*i+3]=t.w;
    }
    float o[48];
#pragma unroll
    for (int j = 0; j < 48; j++) o[j] = 0.f;
#pragma unroll
    for (int i = 0; i < 16; i++) {
        float xi = x[i];
#pragma unroll
        for (int j = 0; j < 48; j++) o[j] = fmaf(xi, sW[i*48+j], o[j]);
    }

    int nn = row >> 8;
    int s0 = (blockIdx.x * 32) & 255;
    float* gdst[3] = { g_k[side], g_q[side], g_v[side] };

#pragma unroll
    for (int a = 0; a < 3; a++) {
        __syncthreads();
#pragma unroll
        for (int d = 0; d < 16; d++) sO[h*548 + rl*17 + d] = o[a*16 + d];
        __syncthreads();
        float* gp = gdst[a] + (((long)(nn*NH))*SW + s0) * DH;
        for (int j = tid; j < 4096; j += 256) {
            int hh = j >> 9, rem = j & 511, ss = rem >> 4, d = rem & 15;
            gp[(long)hh*SW*DH + ss*DH + d] = sO[hh*548 + ss*17 + d];
        }
    }
}

// ---------------------------------------------------------------------------
// Kernel 2: cross attention via tf32 mma. block = (lt, n, side), 8 warps = 8 h.
// QK: 3xTF32 error-split (fp32-grade raw). AV: plain tf32.
// prev/raw staged through smem per 32-s chunk; e->A-frag via quad shuffles.
// ---------------------------------------------------------------------------
#define PL 268    // sP pitch per l:  l*268 + h*33 + s
#define PK 172    // sK pitch per s:  s*172 + h*20 + d
#define PV 168    // sV pitch per s:  s*168 + h*20 + d
#define ATTN_SMEM ((32*PL + 32*PK + 32*PV)*4)   // 77824 B

__global__ __launch_bounds__(256, 2) void attn_kernel(
    const float* __restrict__ prev_l, const float* __restrict__ prev_r,
    float* __restrict__ d_out)
{
    extern __shared__ float sm[];
    float* sP = sm;                  // 32*268
    float* sK = sm + 32*PL;          // 32*172
    float* sV = sm + 32*PL + 32*PK;  // 32*168

    int tid = threadIdx.x;
    int lane = tid & 31;
    int h = tid >> 5;                // warp = head
    int gid = lane >> 2, tig = lane & 3;
    int lt = blockIdx.x, nn = blockIdx.y, side = blockIdx.z;
    int l0 = lt * 32;

    const float* prev = side ? prev_r : prev_l;
    float* raw = d_out + (side ? RAW_R : RAW_L);
    const float* qb = g_q[side];
    const float* kb = g_k[side ^ 1];
    const float* vb = g_v[side ^ 1];

    // ---- Q a-frags (held all kernel): [mt][kt] rows m0+gid/m0+gid+8, cols k0+tig/k0+tig+4
    unsigned qhi[2][2][4], qlo[2][2][4];
    {
        const float* qbase = qb + (((long)(nn*NH + h))*SW + l0)*DH;
#pragma unroll
        for (int mt = 0; mt < 2; mt++) {
#pragma unroll
            for (int kt = 0; kt < 2; kt++) {
                int r0 = mt*16 + gid, c0 = kt*8 + tig;
                float v0 = qbase[r0*DH + c0];
                float v1 = qbase[(r0+8)*DH + c0];
                float v2 = qbase[r0*DH + c0+4];
                float v3 = qbase[(r0+8)*DH + c0+4];
                qhi[mt][kt][0] = f2tf32(v0); qlo[mt][kt][0] = f2tf32(v0 - __uint_as_float(qhi[mt][kt][0]));
                qhi[mt][kt][1] = f2tf32(v1); qlo[mt][kt][1] = f2tf32(v1 - __uint_as_float(qhi[mt][kt][1]));
                qhi[mt][kt][2] = f2tf32(v2); qlo[mt][kt][2] = f2tf32(v2 - __uint_as_float(qhi[mt][kt][2]));
                qhi[mt][kt][3] = f2tf32(v3); qlo[mt][kt][3] = f2tf32(v3 - __uint_as_float(qhi[mt][kt][3]));
            }
        }
    }

    float z00 = 0.f, z01 = 0.f, z10 = 0.f, z11 = 0.f;   // z[mt][row0/row1]
    float acc[2][2][4];
#pragma unroll
    for (int mt = 0; mt < 2; mt++)
#pragma unroll
        for (int nt = 0; nt < 2; nt++)
#pragma unroll
            for (int j = 0; j < 4; j++) acc[mt][nt][j] = 0.f;

    for (int ch = 0; ch < 8; ch++) {
        int s0 = ch * 32;
        __syncthreads();   // prior raw-out + frag reads done before restage

        // ---- stage prev chunk [32l][32s][8h] -> sP[l][h][s]
#pragma unroll
        for (int i = 0; i < 8; i++) {
            int f = i*256 + tid;
            int l = f >> 6, rem = f & 63;
            int s = rem >> 1, hb = (rem & 1) * 4;
            float4 pv = *(const float4*)(prev + (((long)(nn*SW + l0+l))*SW + s0+s)*NH + hb);
            float* dp = sP + l*PL + hb*33 + s;
            dp[0] = pv.x; dp[33] = pv.y; dp[66] = pv.z; dp[99] = pv.w;
        }
        // ---- stage K, V chunks [8h][32s][16d] -> sK/sV [s][h][d]
#pragma unroll
        for (int i = 0; i < 4; i++) {
            int f = i*256 + tid;
            int hh = f >> 7, rem = f & 127;
            int s = rem >> 2, dq = rem & 3;
            long src = (((long)(nn*NH + hh))*SW + s0 + s)*DH + dq*4;
            *(float4*)(sK + s*PK + hh*20 + dq*4) = *(const float4*)(kb + src);
            *(float4*)(sV + s*PV + hh*20 + dq*4) = *(const float4*)(vb + src);
        }
        __syncthreads();

        // ---- QK mma: scores c[mt][st][4] for 32l x 32s (this head)
        float c[2][4][4];
#pragma unroll
        for (int mt = 0; mt < 2; mt++)
#pragma unroll
            for (int st = 0; st < 4; st++)
#pragma unroll
                for (int j = 0; j < 4; j++) c[mt][st][j] = 0.f;

#pragma unroll
        for (int st = 0; st < 4; st++) {
            const float* kr = sK + (st*8 + gid)*PK + h*20;
            float kv0 = kr[tig], kv1 = kr[tig+4], kv2 = kr[tig+8], kv3 = kr[tig+12];
            unsigned kh0 = f2tf32(kv0), kh1 = f2tf32(kv1), kh2 = f2tf32(kv2), kh3 = f2tf32(kv3);
            unsigned kl0 = f2tf32(kv0 - __uint_as_float(kh0));
            unsigned kl1 = f2tf32(kv1 - __uint_as_float(kh1));
            unsigned kl2 = f2tf32(kv2 - __uint_as_float(kh2));
            unsigned kl3 = f2tf32(kv3 - __uint_as_float(kh3));
#pragma unroll
            for (int mt = 0; mt < 2; mt++) {
                mma_tf32(c[mt][st], qhi[mt][0][0], qhi[mt][0][1], qhi[mt][0][2], qhi[mt][0][3], kh0, kh1);
                mma_tf32(c[mt][st], qhi[mt][0][0], qhi[mt][0][1], qhi[mt][0][2], qhi[mt][0][3], kl0, kl1);
                mma_tf32(c[mt][st], qlo[mt][0][0], qlo[mt][0][1], qlo[mt][0][2], qlo[mt][0][3], kh0, kh1);
                mma_tf32(c[mt][st], qhi[mt][1][0], qhi[mt][1][1], qhi[mt][1][2], qhi[mt][1][3], kh2, kh3);
                mma_tf32(c[mt][st], qhi[mt][1][0], qhi[mt][1][1], qhi[mt][1][2], qhi[mt][1][3], kl2, kl3);
                mma_tf32(c[mt][st], qlo[mt][1][0], qlo[mt][1][1], qlo[mt][1][2], qlo[mt][1][3], kh2, kh3);
            }
        }

        // ---- prev add, raw write (to sP in place), exp, z; e replaces c
#pragma unroll
        for (int mt = 0; mt < 2; mt++) {
#pragma unroll
            for (int st = 0; st < 4; st++) {
                float* pp = sP + (mt*16 + gid)*PL + h*33 + st*8 + 2*tig;
                float r0 = c[mt][st][0] + pp[0];
                float r1 = c[mt][st][1] + pp[1];
                float r2 = c[mt][st][2] + pp[8*PL];
                float r3 = c[mt][st][3] + pp[8*PL + 1];
                pp[0] = r0; pp[1] = r1; pp[8*PL] = r2; pp[8*PL + 1] = r3;
                float e0 = __expf(0.25f*r0), e1 = __expf(0.25f*r1);
                float e2 = __expf(0.25f*r2), e3 = __expf(0.25f*r3);
                if (mt == 0) { z00 += e0 + e1; z01 += e2 + e3; }
                else         { z10 += e0 + e1; z11 += e2 + e3; }
                c[mt][st][0] = e0; c[mt][st][1] = e1; c[mt][st][2] = e2; c[mt][st][3] = e3;
            }
        }

        // ---- AV mma: acc[mt][nt] += E(m16 x k8=st) * V(k8 x n8)
        int srcA = (lane & 28) | (tig >> 1);
        int srcB = srcA + 2;
        bool odd = (tig & 1);
#pragma unroll
        for (int st = 0; st < 4; st++) {
            unsigned a[2][4];
#pragma unroll
            for (int mt = 0; mt < 2; mt++) {
                float e0 = c[mt][st][0], e1 = c[mt][st][1];
                float e2 = c[mt][st][2], e3 = c[mt][st][3];
                float g00 = __shfl_sync(0xffffffffu, e0, srcA);
                float g01 = __shfl_sync(0xffffffffu, e1, srcA);
                float g20 = __shfl_sync(0xffffffffu, e2, srcA);
                float g21 = __shfl_sync(0xffffffffu, e3, srcA);
                float h00 = __shfl_sync(0xffffffffu, e0, srcB);
                float h01 = __shfl_sync(0xffffffffu, e1, srcB);
                float h20 = __shfl_sync(0xffffffffu, e2, srcB);
                float h21 = __shfl_sync(0xffffffffu, e3, srcB);
                a[mt][0] = f2tf32(odd ? g01 : g00);
                a[mt][1] = f2tf32(odd ? g21 : g20);
                a[mt][2] = f2tf32(odd ? h01 : h00);
                a[mt][3] = f2tf32(odd ? h21 : h20);
            }
            const float* vr0 = sV + (st*8 + tig)*PV + h*20;
            const float* vr1 = sV + (st*8 + tig + 4)*PV + h*20;
#pragma unroll
            for (int nt = 0; nt < 2; nt++) {
                unsigned vb0 = f2tf32(vr0[nt*8 + gid]);
                unsigned vb1 = f2tf32(vr1[nt*8 + gid]);
                mma_tf32(acc[0][nt], a[0][0], a[0][1], a[0][2], a[0][3], vb0, vb1);
                mma_tf32(acc[1][nt], a[1][0], a[1][1], a[1][2], a[1][3], vb0, vb1);
            }
        }

        // ---- raw out: sP -> gmem (coalesced)
        __syncthreads();
#pragma unroll
        for (int i = 0; i < 8; i++) {
            int f = i*256 + tid;
            int l = f >> 6, rem = f & 63;
            int s = rem >> 1, hb = (rem & 1) * 4;
            float* dp = sP + l*PL + hb*33 + s;
            float4 rv = make_float4(dp[0], dp[33], dp[66], dp[99]);
            *(float4*)(raw + (((long)(nn*SW + l0+l))*SW + s0+s)*NH + hb) = rv;
        }
    }

    // ---- z quad-reduce (cols split across tig lanes)
    z00 += __shfl_xor_sync(0xffffffffu, z00, 1); z00 += __shfl_xor_sync(0xffffffffu, z00, 2);
    z01 += __shfl_xor_sync(0xffffffffu, z01, 1); z01 += __shfl_xor_sync(0xffffffffu, z01, 2);
    z10 += __shfl_xor_sync(0xffffffffu, z10, 1); z10 += __shfl_xor_sync(0xffffffffu, z10, 2);
    z11 += __shfl_xor_sync(0xffffffffu, z11, 1); z11 += __shfl_xor_sync(0xffffffffu, z11, 2);
    float iz[2][2] = { {1.f/z00, 1.f/z01}, {1.f/z10, 1.f/z11} };

    // ---- msg out
    float* mb = g_msg[side];
#pragma unroll
    for (int mt = 0; mt < 2; mt++) {
#pragma unroll
        for (int nt = 0; nt < 2; nt++) {
            long base = ((long)(nn*SW + l0 + mt*16 + gid))*C + h*DH + nt*8 + 2*tig;
            *(float2*)(mb + base)       = make_float2(acc[mt][nt][0]*iz[mt][0], acc[mt][nt][1]*iz[mt][0]);
            *(float2*)(mb + base + 8*C) = make_float2(acc[mt][nt][2]*iz[mt][1], acc[mt][nt][3]*iz[mt][1]);
        }
    }
}

// ---------------------------------------------------------------------------
// Kernel 3: fused LN1 + FFN (tf32 mma.sync) + residual + LN2. 32 rows/block.
// ---------------------------------------------------------------------------
#define XPITCH 132
#define HPITCH 516

__global__ __launch_bounds__(256, 2) void ffn_kernel(
    const float* __restrict__ feat_l, const float* __restrict__ feat_r,
    const float* __restrict__ b1, const float* __restrict__ b2,
    const float* __restrict__ lg1, const float* __restrict__ lb1,
    const float* __restrict__ lg2, const float* __restrict__ lb2,
    float* __restrict__ d_out)
{
    extern __shared__ float smem[];
    float* sX = smem;
    float* sH = smem + 32*XPITCH;
    int tid  = threadIdx.x;
    int side = blockIdx.y;
    const float* feat = side ? feat_r : feat_l;
    const float* msg  = g_msg[side];
    float* outp = d_out + (side ? OUT_R : OUT_L);
    int row0 = blockIdx.x * 32;
    int warp = tid >> 5, lane = tid & 31;
    int gid = lane >> 2, tig = lane & 3;
    int mt = warp & 1, ng = warp >> 1;
    int m0 = mt*16;

    for (int j = tid; j < 1024; j += 256) {
        int r = j >> 5, c4 = j & 31;
        long gi = ((long)(row0+r))*C + c4*4;
        float4 a = *(const float4*)(feat + gi);
        float4 b = *(const float4*)(msg + gi);
        a.x += b.x; a.y += b.y; a.z += b.z; a.w += b.w;
        *(float4*)(&sX[r*XPITCH + c4*4]) = a;
    }
    __syncthreads();

#pragma unroll
    for (int rr = 0; rr < 4; rr++) {
        int r = warp*4 + rr;
        float v0 = sX[r*XPITCH+lane],    v1 = sX[r*XPITCH+lane+32];
        float v2 = sX[r*XPITCH+lane+64], v3 = sX[r*XPITCH+lane+96];
        float sum = v0+v1+v2+v3;
        float sq  = v0*v0+v1*v1+v2*v2+v3*v3;
        for (int o = 16; o; o >>= 1) {
            sum += __shfl_xor_sync(~0u, sum, o);
            sq  += __shfl_xor_sync(~0u, sq,  o);
        }
        float mu = sum*(1.f/128.f);
        float rs = rsqrtf(sq*(1.f/128.f) - mu*mu + 1e-5f);
        sX[r*XPITCH+lane]    = (v0-mu)*rs*lg1[lane]    + lb1[lane];
        sX[r*XPITCH+lane+32] = (v1-mu)*rs*lg1[lane+32] + lb1[lane+32];
        sX[r*XPITCH+lane+64] = (v2-mu)*rs*lg1[lane+64] + lb1[lane+64];
        sX[r*XPITCH+lane+96] = (v3-mu)*rs*lg1[lane+96] + lb1[lane+96];
    }
    __syncthreads();

    {
        float acc[16][4];
#pragma unroll
        for (int t = 0; t < 16; t++)
#pragma unroll
            for (int j = 0; j < 4; j++) acc[t][j] = 0.f;

#pragma unroll 2
        for (int ks = 0; ks < 16; ks++) {
            int k0 = ks*8;
            unsigned a0 = f2tf32(sX[(m0+gid)*XPITCH   + k0 + tig]);
            unsigned a1 = f2tf32(sX[(m0+gid+8)*XPITCH + k0 + tig]);
            unsigned a2 = f2tf32(sX[(m0+gid)*XPITCH   + k0 + tig + 4]);
            unsigned a3 = f2tf32(sX[(m0+gid+8)*XPITCH + k0 + tig + 4]);
            const float4* bp = (const float4*)g_w1f + (ks*32 + ng*8)*32 + lane;
#pragma unroll
            for (int tp = 0; tp < 8; tp++) {
                float4 b = bp[tp*32];
                mma_tf32(acc[2*tp],   a0,a1,a2,a3, __float_as_uint(b.x), __float_as_uint(b.y));
                mma_tf32(acc[2*tp+1], a0,a1,a2,a3, __float_as_uint(b.z), __float_as_uint(b.w));
            }
        }
#pragma unroll
        for (int t = 0; t < 16; t++) {
            int col = ng*128 + t*8 + 2*tig;
            float h00 = acc[t][0] + b1[col];
            float h01 = acc[t][1] + b1[col+1];
            float h10 = acc[t][2] + b1[col];
            float h11 = acc[t][3] + b1[col+1];
            h00 = 0.5f*h00*(1.f + erff(h00*0.70710678118654752f));
            h01 = 0.5f*h01*(1.f + erff(h01*0.70710678118654752f));
            h10 = 0.5f*h10*(1.f + erff(h10*0.70710678118654752f));
            h11 = 0.5f*h11*(1.f + erff(h11*0.70710678118654752f));
            float2 lo = make_float2(__uint_as_float(f2tf32(h00)), __uint_as_float(f2tf32(h01)));
            float2 hi = make_float2(__uint_as_float(f2tf32(h10)), __uint_as_float(f2tf32(h11)));
            *(float2*)(&sH[(m0+gid)*HPITCH   + col]) = lo;
            *(float2*)(&sH[(m0+gid+8)*HPITCH + col]) = hi;
        }
    }
    __syncthreads();

    float acc2[4][4];
#pragma unroll
    for (int t = 0; t < 4; t++)
#pragma unroll
        for (int j = 0; j < 4; j++) acc2[t][j] = 0.f;
    {
        const unsigned* sHi = (const unsigned*)sH;
#pragma unroll 4
        for (int ks = 0; ks < 64; ks++) {
            int k0 = ks*8;
            unsigned a0 = sHi[(m0+gid)*HPITCH   + k0 + tig];
            unsigned a1 = sHi[(m0+gid+8)*HPITCH + k0 + tig];
            unsigned a2 = sHi[(m0+gid)*HPITCH   + k0 + tig + 4];
            unsigned a3 = sHi[(m0+gid+8)*HPITCH + k0 + tig + 4];
            const float4* bp = (const float4*)g_w2f + (ks*8 + ng*2)*32 + lane;
            float4 b0v = bp[0];
            float4 b1v = bp[32];
            mma_tf32(acc2[0], a0,a1,a2,a3, __float_as_uint(b0v.x), __float_as_uint(b0v.y));
            mma_tf32(acc2[1], a0,a1,a2,a3, __float_as_uint(b0v.z), __float_as_uint(b0v.w));
            mma_tf32(acc2[2], a0,a1,a2,a3, __float_as_uint(b1v.x), __float_as_uint(b1v.y));
            mma_tf32(acc2[3], a0,a1,a2,a3, __float_as_uint(b1v.z), __float_as_uint(b1v.w));
        }
    }
    __syncthreads();

#pragma unroll
    for (int t = 0; t < 4; t++) {
        int col = ng*32 + t*8 + 2*tig;
        int r0 = m0+gid, r1 = m0+gid+8;
        float2 lo, hi;
        lo.x = acc2[t][0] + b2[col]   + sX[r0*XPITCH + col];
        lo.y = acc2[t][1] + b2[col+1] + sX[r0*XPITCH + col + 1];
        hi.x = acc2[t][2] + b2[col]   + sX[r1*XPITCH + col];
        hi.y = acc2[t][3] + b2[col+1] + sX[r1*XPITCH + col + 1];
        *(float2*)(&sH[r0*XPITCH + col]) = lo;
        *(float2*)(&sH[r1*XPITCH + col]) = hi;
    }
    __syncthreads();

#pragma unroll
    for (int rr = 0; rr < 4; rr++) {
        int r = warp*4 + rr;
        float v0 = sH[r*XPITCH+lane],    v1 = sH[r*XPITCH+lane+32];
        float v2 = sH[r*XPITCH+lane+64], v3 = sH[r*XPITCH+lane+96];
        float sum = v0+v1+v2+v3;
        float sq  = v0*v0+v1*v1+v2*v2+v3*v3;
        for (int o = 16; o; o >>= 1) {
            sum += __shfl_xor_sync(~0u, sum, o);
            sq  += __shfl_xor_sync(~0u, sq,  o);
        }
        float mu = sum*(1.f/128.f);
        float rs = rsqrtf(sq*(1.f/128.f) - mu*mu + 1e-5f);
        long go = ((long)(row0+r))*C;
        outp[go+lane]    = (v0-mu)*rs*lg2[lane]    + lb2[lane];
        outp[go+lane+32] = (v1-mu)*rs*lg2[lane+32] + lb2[lane+32];
        outp[go+lane+64] = (v2-mu)*rs*lg2[lane+64] + lb2[lane+64];
        outp[go+lane+96] = (v3-mu)*rs*lg2[lane+96] + lb2[lane+96];
    }
}

// ---------------------------------------------------------------------------
extern "C" void kernel_launch(void* const* d_in, const int* in_sizes, int n_in,
                              void* d_out, int out_size)
{
    const float* feat_l = (const float*)d_in[0];
    const float* feat_r = (const float*)d_in[1];
    const float* prev_l = (const float*)d_in[2];
    const float* prev_r = (const float*)d_in[3];
    const float* kqv_w  = (const float*)d_in[4];
    const float* ff_w1  = (const float*)d_in[5];
    const float* ff_b1  = (const float*)d_in[6];
    const float* ff_w2  = (const float*)d_in[7];
    const float* ff_b2  = (const float*)d_in[8];
    const float* ln1_g  = (const float*)d_in[9];
    const float* ln1_b  = (const float*)d_in[10];
    const float* ln2_g  = (const float*)d_in[11];
    const float* ln2_b  = (const float*)d_in[12];
    float* out = (float*)d_out;

    const int FFN_SMEM = (32*XPITCH + 32*HPITCH) * 4;   // 82944 B
    cudaFuncSetAttribute(ffn_kernel, cudaFuncAttributeMaxDynamicSharedMemorySize, FFN_SMEM);
    cudaFuncSetAttribute(attn_kernel, cudaFuncAttributeMaxDynamicSharedMemorySize, ATTN_SMEM);

    prep_kernel<<<128, 256>>>(ff_w1, ff_w2);
    proj_kernel<<<dim3(NTOK/32, 2), 256>>>(feat_l, feat_r, kqv_w);
    attn_kernel<<<dim3(SW/32, NSEQ, 2), 256, ATTN_SMEM>>>(prev_l, prev_r, out);
    ffn_kernel<<<dim3(NTOK/32, 2), 256, FFN_SMEM>>>(
        feat_l, feat_r, ff_b1, ff_b2,
        ln1_g, ln1_b, ln2_g, ln2_b, out);
}

// round 9
// speedup vs baseline: 3.7479x; 1.0634x over previous
#include <cuda_runtime.h>
#include <cuda_bf16.h>
#include <math.h>

#define NSEQ 80
#define SW 256
#define C 128
#define NH 8
#define DH 16
#define FF 512
#define NTOK (NSEQ*SW)          // 20480
#define TOKC (NTOK*C)           // 2621440

#define OUT_L 0
#define OUT_R TOKC
#define RAW_L (2*TOKC)
#define RAW_R (2*TOKC + NSEQ*SW*SW*NH)

// Scratch (device globals: allocation-free)
__device__ float g_k[2][TOKC];
__device__ float g_q[2][TOKC];
__device__ float g_v[2][TOKC];
__device__ float g_msg[2][TOKC];
__device__ float g_w1f[16*32*32*4];   // W1 tf32 frag layout
__device__ float g_w2f[64*8*32*4];    // W2 tf32 frag layout

// ---- mma helpers ----
__device__ __forceinline__ unsigned f2tf32(float x) {
    unsigned r; asm("cvt.rna.tf32.f32 %0, %1;" : "=r"(r) : "f"(x)); return r;
}
__device__ __forceinline__ void mma_tf32(float* c,
    unsigned a0, unsigned a1, unsigned a2, unsigned a3,
    unsigned b0, unsigned b1)
{
    asm("mma.sync.aligned.m16n8k8.row.col.f32.tf32.tf32.f32 "
        "{%0,%1,%2,%3},{%4,%5,%6,%7},{%8,%9},{%0,%1,%2,%3};"
        : "+f"(c[0]), "+f"(c[1]), "+f"(c[2]), "+f"(c[3])
        : "r"(a0), "r"(a1), "r"(a2), "r"(a3), "r"(b0), "r"(b1));
}
__device__ __forceinline__ void mma_bf16(float* c,
    const unsigned* a, unsigned b0, unsigned b1)
{
    asm("mma.sync.aligned.m16n8k16.row.col.f32.bf16.bf16.f32 "
        "{%0,%1,%2,%3},{%4,%5,%6,%7},{%8,%9},{%0,%1,%2,%3};"
        : "+f"(c[0]), "+f"(c[1]), "+f"(c[2]), "+f"(c[3])
        : "r"(a[0]), "r"(a[1]), "r"(a[2]), "r"(a[3]), "r"(b0), "r"(b1));
}
// split float2 into bf16x2 hi + bf16x2 residual
__device__ __forceinline__ void bfsplit(float2 v, unsigned& hi, unsigned& lo) {
    __nv_bfloat162 h = __floats2bfloat162_rn(v.x, v.y);
    float2 hf = __bfloat1622float2(h);
    __nv_bfloat162 l = __floats2bfloat162_rn(v.x - hf.x, v.y - hf.y);
    hi = *reinterpret_cast<unsigned*>(&h);
    lo = *reinterpret_cast<unsigned*>(&l);
}

// ---------------------------------------------------------------------------
// Kernel 0: W1/W2 -> tf32 fragment layouts.
// ---------------------------------------------------------------------------
__global__ __launch_bounds__(256) void prep_kernel(
    const float* __restrict__ w1, const float* __restrict__ w2)
{
    int i = blockIdx.x * 256 + threadIdx.x;     // 0..32767
    if (i < 16384) {
        int lane = i & 31, tp = (i >> 5) & 31, ks = i >> 10;
        int gid = lane >> 2, tig = lane & 3;
        int k0 = ks*8, n0 = (2*tp)*8, n1 = (2*tp+1)*8;
        float4 o;
        o.x = __uint_as_float(f2tf32(w1[(k0+tig)*FF   + n0+gid]));
        o.y = __uint_as_float(f2tf32(w1[(k0+tig+4)*FF + n0+gid]));
        o.z = __uint_as_float(f2tf32(w1[(k0+tig)*FF   + n1+gid]));
        o.w = __uint_as_float(f2tf32(w1[(k0+tig+4)*FF + n1+gid]));
        ((float4*)g_w1f)[i] = o;
    } else {
        int j = i - 16384;
        int lane = j & 31, tp = (j >> 5) & 7, ks = j >> 8;
        int gid = lane >> 2, tig = lane & 3;
        int k0 = ks*8, n0 = (2*tp)*8, n1 = (2*tp+1)*8;
        float4 o;
        o.x = __uint_as_float(f2tf32(w2[(k0+tig)*C   + n0+gid]));
        o.y = __uint_as_float(f2tf32(w2[(k0+tig+4)*C + n0+gid]));
        o.z = __uint_as_float(f2tf32(w2[(k0+tig)*C   + n1+gid]));
        o.w = __uint_as_float(f2tf32(w2[(k0+tig+4)*C + n1+gid]));
        ((float4*)g_w2f)[j] = o;
    }
}

// ---------------------------------------------------------------------------
// Kernel 1: per-head KQV projection with coalesced smem-staged stores.
// ---------------------------------------------------------------------------
__global__ __launch_bounds__(256) void proj_kernel(
    const float* __restrict__ feat_l, const float* __restrict__ feat_r,
    const float* __restrict__ kqv_w)
{
    __shared__ float sW[16*48];
    __shared__ float sO[8*548];
    int tid = threadIdx.x;
    for (int i = tid; i < 16*48; i += 256) sW[i] = kqv_w[i];

    int side = blockIdx.y;
    const float* feat = side ? feat_r : feat_l;
    int rl = tid >> 3;
    int h  = tid & 7;
    int row = blockIdx.x * 32 + rl;
    __syncthreads();

    float x[16];
    const float4* xp = (const float4*)(feat + (long)row*C + h*DH);
#pragma unroll
    for (int i = 0; i < 4; i++) {
        float4 t = xp[i];
        x[4*i+0]=t.x; x[4*i+1]=t.y; x[4*i+2]=t.z; x[4*i+3]=t.w;
    }
    float o[48];
#pragma unroll
    for (int j = 0; j < 48; j++) o[j] = 0.f;
#pragma unroll
    for (int i = 0; i < 16; i++) {
        float xi = x[i];
#pragma unroll
        for (int j = 0; j < 48; j++) o[j] = fmaf(xi, sW[i*48+j], o[j]);
    }

    int nn = row >> 8;
    int s0 = (blockIdx.x * 32) & 255;
    float* gdst[3] = { g_k[side], g_q[side], g_v[side] };

#pragma unroll
    for (int a = 0; a < 3; a++) {
        __syncthreads();
#pragma unroll
        for (int d = 0; d < 16; d++) sO[h*548 + rl*17 + d] = o[a*16 + d];
        __syncthreads();
        float* gp = gdst[a] + (((long)(nn*NH))*SW + s0) * DH;
        for (int j = tid; j < 4096; j += 256) {
            int hh = j >> 9, rem = j & 511, ss = rem >> 4, d = rem & 15;
            gp[(long)hh*SW*DH + ss*DH + d] = sO[hh*548 + ss*17 + d];
        }
    }
}

// ---------------------------------------------------------------------------
// Kernel 2: cross attention. QK: bf16 2-split m16n8k16 (3 terms, fp32-grade).
// AV: tf32 k8. prev/raw staged via smem; e->A-frag via quad shuffles.
// ---------------------------------------------------------------------------
#define PL 268    // sP pitch per l:  l*268 + h*33 + s
#define PK 172    // sK pitch per s:  s*172 + h*20 + d
#define PV 168    // sV pitch per s:  s*168 + h*20 + d
#define ATTN_SMEM ((32*PL + 32*PK + 32*PV)*4)   // 77824 B

__global__ __launch_bounds__(256, 2) void attn_kernel(
    const float* __restrict__ prev_l, const float* __restrict__ prev_r,
    float* __restrict__ d_out)
{
    extern __shared__ float sm[];
    float* sP = sm;                  // 32*268
    float* sK = sm + 32*PL;          // 32*172
    float* sV = sm + 32*PL + 32*PK;  // 32*168

    int tid = threadIdx.x;
    int lane = tid & 31;
    int h = tid >> 5;                // warp = head
    int gid = lane >> 2, tig = lane & 3;
    int lt = blockIdx.x, nn = blockIdx.y, side = blockIdx.z;
    int l0 = lt * 32;

    const float* prev = side ? prev_r : prev_l;
    float* raw = d_out + (side ? RAW_R : RAW_L);
    const float* qb = g_q[side];
    const float* kb = g_k[side ^ 1];
    const float* vb = g_v[side ^ 1];

    // ---- Q a-frags (k16 over full DH): a0..a3 = (row gid / gid+8) x (cols 2tig..,+8..)
    unsigned qhi[2][4], qlo[2][4];
    {
        const float* qbase = qb + (((long)(nn*NH + h))*SW + l0)*DH;
#pragma unroll
        for (int mt = 0; mt < 2; mt++) {
            const float* r0 = qbase + (mt*16 + gid)*DH;
            const float* r1 = r0 + 8*DH;
            bfsplit(*(const float2*)(r0 + 2*tig),     qhi[mt][0], qlo[mt][0]);
            bfsplit(*(const float2*)(r1 + 2*tig),     qhi[mt][1], qlo[mt][1]);
            bfsplit(*(const float2*)(r0 + 2*tig + 8), qhi[mt][2], qlo[mt][2]);
            bfsplit(*(const float2*)(r1 + 2*tig + 8), qhi[mt][3], qlo[mt][3]);
        }
    }

    float z00 = 0.f, z01 = 0.f, z10 = 0.f, z11 = 0.f;
    float acc[2][2][4];
#pragma unroll
    for (int mt = 0; mt < 2; mt++)
#pragma unroll
        for (int nt = 0; nt < 2; nt++)
#pragma unroll
            for (int j = 0; j < 4; j++) acc[mt][nt][j] = 0.f;

    for (int ch = 0; ch < 8; ch++) {
        int s0 = ch * 32;
        __syncthreads();

        // ---- stage prev chunk [32l][32s][8h] -> sP[l][h][s]
#pragma unroll
        for (int i = 0; i < 8; i++) {
            int f = i*256 + tid;
            int l = f >> 6, rem = f & 63;
            int s = rem >> 1, hb = (rem & 1) * 4;
            float4 pv = *(const float4*)(prev + (((long)(nn*SW + l0+l))*SW + s0+s)*NH + hb);
            float* dp = sP + l*PL + hb*33 + s;
            dp[0] = pv.x; dp[33] = pv.y; dp[66] = pv.z; dp[99] = pv.w;
        }
        // ---- stage K, V chunks
#pragma unroll
        for (int i = 0; i < 4; i++) {
            int f = i*256 + tid;
            int hh = f >> 7, rem = f & 127;
            int s = rem >> 2, dq = rem & 3;
            long src = (((long)(nn*NH + hh))*SW + s0 + s)*DH + dq*4;
            *(float4*)(sK + s*PK + hh*20 + dq*4) = *(const float4*)(kb + src);
            *(float4*)(sV + s*PV + hh*20 + dq*4) = *(const float4*)(vb + src);
        }
        __syncthreads();

        // ---- QK mma (bf16 split, k16): c[mt][st][4]
        float c[2][4][4];
#pragma unroll
        for (int mt = 0; mt < 2; mt++)
#pragma unroll
            for (int st = 0; st < 4; st++)
#pragma unroll
                for (int j = 0; j < 4; j++) c[mt][st][j] = 0.f;

#pragma unroll
        for (int st = 0; st < 4; st++) {
            const float* kr = sK + (st*8 + gid)*PK + h*20;
            unsigned k0h, k0l, k1h, k1l;
            bfsplit(*(const float2*)(kr + 2*tig),     k0h, k0l);
            bfsplit(*(const float2*)(kr + 2*tig + 8), k1h, k1l);
#pragma unroll
            for (int mt = 0; mt < 2; mt++) {
                mma_bf16(c[mt][st], qhi[mt], k0h, k1h);
                mma_bf16(c[mt][st], qhi[mt], k0l, k1l);
                mma_bf16(c[mt][st], qlo[mt], k0h, k1h);
            }
        }

        // ---- prev add, raw (in sP), exp, z
#pragma unroll
        for (int mt = 0; mt < 2; mt++) {
#pragma unroll
            for (int st = 0; st < 4; st++) {
                float* pp = sP + (mt*16 + gid)*PL + h*33 + st*8 + 2*tig;
                float r0 = c[mt][st][0] + pp[0];
                float r1 = c[mt][st][1] + pp[1];
                float r2 = c[mt][st][2] + pp[8*PL];
                float r3 = c[mt][st][3] + pp[8*PL + 1];
                pp[0] = r0; pp[1] = r1; pp[8*PL] = r2; pp[8*PL + 1] = r3;
                float e0 = __expf(0.25f*r0), e1 = __expf(0.25f*r1);
                float e2 = __expf(0.25f*r2), e3 = __expf(0.25f*r3);
                if (mt == 0) { z00 += e0 + e1; z01 += e2 + e3; }
                else         { z10 += e0 + e1; z11 += e2 + e3; }
                c[mt][st][0] = e0; c[mt][st][1] = e1; c[mt][st][2] = e2; c[mt][st][3] = e3;
            }
        }

        // ---- AV mma (tf32 k8)
        int srcA = (lane & 28) | (tig >> 1);
        int srcB = srcA + 2;
        bool odd = (tig & 1);
#pragma unroll
        for (int st = 0; st < 4; st++) {
            unsigned a[2][4];
#pragma unroll
            for (int mt = 0; mt < 2; mt++) {
                float e0 = c[mt][st][0], e1 = c[mt][st][1];
                float e2 = c[mt][st][2], e3 = c[mt][st][3];
                float g00 = __shfl_sync(0xffffffffu, e0, srcA);
                float g01 = __shfl_sync(0xffffffffu, e1, srcA);
                float g20 = __shfl_sync(0xffffffffu, e2, srcA);
                float g21 = __shfl_sync(0xffffffffu, e3, srcA);
                float h00 = __shfl_sync(0xffffffffu, e0, srcB);
                float h01 = __shfl_sync(0xffffffffu, e1, srcB);
                float h20 = __shfl_sync(0xffffffffu, e2, srcB);
                float h21 = __shfl_sync(0xffffffffu, e3, srcB);
                a[mt][0] = f2tf32(odd ? g01 : g00);
                a[mt][1] = f2tf32(odd ? g21 : g20);
                a[mt][2] = f2tf32(odd ? h01 : h00);
                a[mt][3] = f2tf32(odd ? h21 : h20);
            }
            const float* vr0 = sV + (st*8 + tig)*PV + h*20;
            const float* vr1 = sV + (st*8 + tig + 4)*PV + h*20;
#pragma unroll
            for (int nt = 0; nt < 2; nt++) {
                unsigned vb0 = f2tf32(vr0[nt*8 + gid]);
                unsigned vb1 = f2tf32(vr1[nt*8 + gid]);
                mma_tf32(acc[0][nt], a[0][0], a[0][1], a[0][2], a[0][3], vb0, vb1);
                mma_tf32(acc[1][nt], a[1][0], a[1][1], a[1][2], a[1][3], vb0, vb1);
            }
        }

        // ---- raw out: sP -> gmem (coalesced)
        __syncthreads();
#pragma unroll
        for (int i = 0; i < 8; i++) {
            int f = i*256 + tid;
            int l = f >> 6, rem = f & 63;
            int s = rem >> 1, hb = (rem & 1) * 4;
            float* dp = sP + l*PL + hb*33 + s;
            float4 rv = make_float4(dp[0], dp[33], dp[66], dp[99]);
            *(float4*)(raw + (((long)(nn*SW + l0+l))*SW + s0+s)*NH + hb) = rv;
        }
    }

    // ---- z quad-reduce
    z00 += __shfl_xor_sync(0xffffffffu, z00, 1); z00 += __shfl_xor_sync(0xffffffffu, z00, 2);
    z01 += __shfl_xor_sync(0xffffffffu, z01, 1); z01 += __shfl_xor_sync(0xffffffffu, z01, 2);
    z10 += __shfl_xor_sync(0xffffffffu, z10, 1); z10 += __shfl_xor_sync(0xffffffffu, z10, 2);
    z11 += __shfl_xor_sync(0xffffffffu, z11, 1); z11 += __shfl_xor_sync(0xffffffffu, z11, 2);
    float iz[2][2] = { {1.f/z00, 1.f/z01}, {1.f/z10, 1.f/z11} };

    // ---- msg out
    float* mb = g_msg[side];
#pragma unroll
    for (int mt = 0; mt < 2; mt++) {
#pragma unroll
        for (int nt = 0; nt < 2; nt++) {
            long base = ((long)(nn*SW + l0 + mt*16 + gid))*C + h*DH + nt*8 + 2*tig;
            *(float2*)(mb + base)       = make_float2(acc[mt][nt][0]*iz[mt][0], acc[mt][nt][1]*iz[mt][0]);
            *(float2*)(mb + base + 8*C) = make_float2(acc[mt][nt][2]*iz[mt][1], acc[mt][nt][3]*iz[mt][1]);
        }
    }
}

// ---------------------------------------------------------------------------
// Kernel 3: fused LN1 + FFN (tf32 mma) + residual + LN2. 32 rows/block.
// Re-tiled: each warp owns a UNIQUE col slice (64 cols GEMM1 / 16 cols GEMM2)
// across all 32 rows -> no duplicate B-fragment loads.
// ---------------------------------------------------------------------------
#define XPITCH 132
#define HPITCH 516

__global__ __launch_bounds__(256, 2) void ffn_kernel(
    const float* __restrict__ feat_l, const float* __restrict__ feat_r,
    const float* __restrict__ b1, const float* __restrict__ b2,
    const float* __restrict__ lg1, const float* __restrict__ lb1,
    const float* __restrict__ lg2, const float* __restrict__ lb2,
    float* __restrict__ d_out)
{
    extern __shared__ float smem[];
    float* sX = smem;
    float* sH = smem + 32*XPITCH;
    int tid  = threadIdx.x;
    int side = blockIdx.y;
    const float* feat = side ? feat_r : feat_l;
    const float* msg  = g_msg[side];
    float* outp = d_out + (side ? OUT_R : OUT_L);
    int row0 = blockIdx.x * 32;
    int warp = tid >> 5, lane = tid & 31;
    int gid = lane >> 2, tig = lane & 3;

    for (int j = tid; j < 1024; j += 256) {
        int r = j >> 5, c4 = j & 31;
        long gi = ((long)(row0+r))*C + c4*4;
        float4 a = *(const float4*)(feat + gi);
        float4 b = *(const float4*)(msg + gi);
        a.x += b.x; a.y += b.y; a.z += b.z; a.w += b.w;
        *(float4*)(&sX[r*XPITCH + c4*4]) = a;
    }
    __syncthreads();

#pragma unroll
    for (int rr = 0; rr < 4; rr++) {
        int r = warp*4 + rr;
        float v0 = sX[r*XPITCH+lane],    v1 = sX[r*XPITCH+lane+32];
        float v2 = sX[r*XPITCH+lane+64], v3 = sX[r*XPITCH+lane+96];
        float sum = v0+v1+v2+v3;
        float sq  = v0*v0+v1*v1+v2*v2+v3*v3;
        for (int o = 16; o; o >>= 1) {
            sum += __shfl_xor_sync(~0u, sum, o);
            sq  += __shfl_xor_sync(~0u, sq,  o);
        }
        float mu = sum*(1.f/128.f);
        float rs = rsqrtf(sq*(1.f/128.f) - mu*mu + 1e-5f);
        sX[r*XPITCH+lane]    = (v0-mu)*rs*lg1[lane]    + lb1[lane];
        sX[r*XPITCH+lane+32] = (v1-mu)*rs*lg1[lane+32] + lb1[lane+32];
        sX[r*XPITCH+lane+64] = (v2-mu)*rs*lg1[lane+64] + lb1[lane+64];
        sX[r*XPITCH+lane+96] = (v3-mu)*rs*lg1[lane+96] + lb1[lane+96];
    }
    __syncthreads();

    // GEMM1: warp = cols [warp*64, +64) x rows 0..31 (mt = m16 half)
    {
        float acc[2][8][4];
#pragma unroll
        for (int mt = 0; mt < 2; mt++)
#pragma unroll
            for (int t = 0; t < 8; t++)
#pragma unroll
                for (int j = 0; j < 4; j++) acc[mt][t][j] = 0.f;

#pragma unroll 2
        for (int ks = 0; ks < 16; ks++) {
            int k0 = ks*8;
            unsigned a[2][4];
#pragma unroll
            for (int mt = 0; mt < 2; mt++) {
                a[mt][0] = f2tf32(sX[(mt*16+gid)*XPITCH   + k0 + tig]);
                a[mt][1] = f2tf32(sX[(mt*16+gid+8)*XPITCH + k0 + tig]);
                a[mt][2] = f2tf32(sX[(mt*16+gid)*XPITCH   + k0 + tig + 4]);
                a[mt][3] = f2tf32(sX[(mt*16+gid+8)*XPITCH + k0 + tig + 4]);
            }
            const float4* bp = (const float4*)g_w1f + (ks*32 + warp*4)*32 + lane;
#pragma unroll
            for (int j4 = 0; j4 < 4; j4++) {
                float4 b = bp[j4*32];
#pragma unroll
                for (int mt = 0; mt < 2; mt++) {
                    mma_tf32(acc[mt][2*j4],   a[mt][0],a[mt][1],a[mt][2],a[mt][3], __float_as_uint(b.x), __float_as_uint(b.y));
                    mma_tf32(acc[mt][2*j4+1], a[mt][0],a[mt][1],a[mt][2],a[mt][3], __float_as_uint(b.z), __float_as_uint(b.w));
                }
            }
        }
#pragma unroll
        for (int mt = 0; mt < 2; mt++) {
#pragma unroll
            for (int t = 0; t < 8; t++) {
                int col = warp*64 + t*8 + 2*tig;
                int r0 = mt*16 + gid, r1 = r0 + 8;
                float h00 = acc[mt][t][0] + b1[col];
                float h01 = acc[mt][t][1] + b1[col+1];
                float h10 = acc[mt][t][2] + b1[col];
                float h11 = acc[mt][t][3] + b1[col+1];
                h00 = 0.5f*h00*(1.f + erff(h00*0.70710678118654752f));
                h01 = 0.5f*h01*(1.f + erff(h01*0.70710678118654752f));
                h10 = 0.5f*h10*(1.f + erff(h10*0.70710678118654752f));
                h11 = 0.5f*h11*(1.f + erff(h11*0.70710678118654752f));
                *(float2*)(&sH[r0*HPITCH + col]) =
                    make_float2(__uint_as_float(f2tf32(h00)), __uint_as_float(f2tf32(h01)));
                *(float2*)(&sH[r1*HPITCH + col]) =
                    make_float2(__uint_as_float(f2tf32(h10)), __uint_as_float(f2tf32(h11)));
            }
        }
    }
    __syncthreads();

    // GEMM2: warp = cols [warp*16, +16) x rows 0..31
    float acc2[2][2][4];
#pragma unroll
    for (int mt = 0; mt < 2; mt++)
#pragma unroll
        for (int nt = 0; nt < 2; nt++)
#pragma unroll
            for (int j = 0; j < 4; j++) acc2[mt][nt][j] = 0.f;
    {
        const unsigned* sHi = (const unsigned*)sH;
#pragma unroll 4
        for (int ks = 0; ks < 64; ks++) {
            int k0 = ks*8;
            unsigned a[2][4];
#pragma unroll
            for (int mt = 0; mt < 2; mt++) {
                a[mt][0] = sHi[(mt*16+gid)*HPITCH   + k0 + tig];
                a[mt][1] = sHi[(mt*16+gid+8)*HPITCH + k0 + tig];
                a[mt][2] = sHi[(mt*16+gid)*HPITCH   + k0 + tig + 4];
                a[mt][3] = sHi[(mt*16+gid+8)*HPITCH + k0 + tig + 4];
            }
            float4 b = ((const float4*)g_w2f)[(ks*8 + warp)*32 + lane];
#pragma unroll
            for (int mt = 0; mt < 2; mt++) {
                mma_tf32(acc2[mt][0], a[mt][0],a[mt][1],a[mt][2],a[mt][3], __float_as_uint(b.x), __float_as_uint(b.y));
                mma_tf32(acc2[mt][1], a[mt][0],a[mt][1],a[mt][2],a[mt][3], __float_as_uint(b.z), __float_as_uint(b.w));
            }
        }
    }
    __syncthreads();   // reads of sH done; reuse as out tile

#pragma unroll
    for (int mt = 0; mt < 2; mt++) {
#pragma unroll
        for (int nt = 0; nt < 2; nt++) {
            int col = warp*16 + nt*8 + 2*tig;
            int r0 = mt*16 + gid, r1 = r0 + 8;
            float2 lo, hi;
            lo.x = acc2[mt][nt][0] + b2[col]   + sX[r0*XPITCH + col];
            lo.y = acc2[mt][nt][1] + b2[col+1] + sX[r0*XPITCH + col + 1];
            hi.x = acc2[mt][nt][2] + b2[col]   + sX[r1*XPITCH + col];
            hi.y = acc2[mt][nt][3] + b2[col+1] + sX[r1*XPITCH + col + 1];
            *(float2*)(&sH[r0*XPITCH + col]) = lo;
            *(float2*)(&sH[r1*XPITCH + col]) = hi;
        }
    }
    __syncthreads();

#pragma unroll
    for (int rr = 0; rr < 4; rr++) {
        int r = warp*4 + rr;
        float v0 = sH[r*XPITCH+lane],    v1 = sH[r*XPITCH+lane+32];
        float v2 = sH[r*XPITCH+lane+64], v3 = sH[r*XPITCH+lane+96];
        float sum = v0+v1+v2+v3;
        float sq  = v0*v0+v1*v1+v2*v2+v3*v3;
        for (int o = 16; o; o >>= 1) {
            sum += __shfl_xor_sync(~0u, sum, o);
            sq  += __shfl_xor_sync(~0u, sq,  o);
        }
        float mu = sum*(1.f/128.f);
        float rs = rsqrtf(sq*(1.f/128.f) - mu*mu + 1e-5f);
        long go = ((long)(row0+r))*C;
        outp[go+lane]    = (v0-mu)*rs*lg2[lane]    + lb2[lane];
        outp[go+lane+32] = (v1-mu)*rs*lg2[lane+32] + lb2[lane+32];
        outp[go+lane+64] = (v2-mu)*rs*lg2[lane+64] + lb2[lane+64];
        outp[go+lane+96] = (v3-mu)*rs*lg2[lane+96] + lb2[lane+96];
    }
}

// ---------------------------------------------------------------------------
extern "C" void kernel_launch(void* const* d_in, const int* in_sizes, int n_in,
                              void* d_out, int out_size)
{
    const float* feat_l = (const float*)d_in[0];
    const float* feat_r = (const float*)d_in[1];
    const float* prev_l = (const float*)d_in[2];
    const float* prev_r = (const float*)d_in[3];
    const float* kqv_w  = (const float*)d_in[4];
    const float* ff_w1  = (const float*)d_in[5];
    const float* ff_b1  = (const float*)d_in[6];
    const float* ff_w2  = (const float*)d_in[7];
    const float* ff_b2  = (const float*)d_in[8];
    const float* ln1_g  = (const float*)d_in[9];
    const float* ln1_b  = (const float*)d_in[10];
    const float* ln2_g  = (const float*)d_in[11];
    const float* ln2_b  = (const float*)d_in[12];
    float* out = (float*)d_out;

    const int FFN_SMEM = (32*XPITCH + 32*HPITCH) * 4;   // 82944 B
    cudaFuncSetAttribute(ffn_kernel, cudaFuncAttributeMaxDynamicSharedMemorySize, FFN_SMEM);
    cudaFuncSetAttribute(attn_kernel, cudaFuncAttributeMaxDynamicSharedMemorySize, ATTN_SMEM);

    prep_kernel<<<128, 256>>>(ff_w1, ff_w2);
    proj_kernel<<<dim3(NTOK/32, 2), 256>>>(feat_l, feat_r, kqv_w);
    attn_kernel<<<dim3(SW/32, NSEQ, 2), 256, ATTN_SMEM>>>(prev_l, prev_r, out);
    ffn_kernel<<<dim3(NTOK/32, 2), 256, FFN_SMEM>>>(
        feat_l, feat_r, ff_b1, ff_b2,
        ln1_g, ln1_b, ln2_g, ln2_b, out);
}

// round 10
// speedup vs baseline: 3.7493x; 1.0004x over previous
#include <cuda_runtime.h>
#include <cuda_bf16.h>
#include <math.h>

#define NSEQ 80
#define SW 256
#define C 128
#define NH 8
#define DH 16
#define FF 512
#define NTOK (NSEQ*SW)          // 20480
#define TOKC (NTOK*C)           // 2621440

#define OUT_L 0
#define OUT_R TOKC
#define RAW_L (2*TOKC)
#define RAW_R (2*TOKC + NSEQ*SW*SW*NH)

// Scratch (device globals: allocation-free)
__device__ float g_k[2][TOKC];
__device__ float g_q[2][TOKC];
__device__ float g_v[2][TOKC];
__device__ float g_msg[2][TOKC];
__device__ float g_w1f[16*32*32*4];   // W1 tf32 frag layout
__device__ float g_w2f[64*8*32*4];    // W2 tf32 frag layout

// ---- mma helpers ----
__device__ __forceinline__ unsigned f2tf32(float x) {
    unsigned r; asm("cvt.rna.tf32.f32 %0, %1;" : "=r"(r) : "f"(x)); return r;
}
__device__ __forceinline__ void mma_tf32(float* c,
    unsigned a0, unsigned a1, unsigned a2, unsigned a3,
    unsigned b0, unsigned b1)
{
    asm("mma.sync.aligned.m16n8k8.row.col.f32.tf32.tf32.f32 "
        "{%0,%1,%2,%3},{%4,%5,%6,%7},{%8,%9},{%0,%1,%2,%3};"
        : "+f"(c[0]), "+f"(c[1]), "+f"(c[2]), "+f"(c[3])
        : "r"(a0), "r"(a1), "r"(a2), "r"(a3), "r"(b0), "r"(b1));
}
__device__ __forceinline__ void mma_bf16(float* c,
    const unsigned* a, unsigned b0, unsigned b1)
{
    asm("mma.sync.aligned.m16n8k16.row.col.f32.bf16.bf16.f32 "
        "{%0,%1,%2,%3},{%4,%5,%6,%7},{%8,%9},{%0,%1,%2,%3};"
        : "+f"(c[0]), "+f"(c[1]), "+f"(c[2]), "+f"(c[3])
        : "r"(a[0]), "r"(a[1]), "r"(a[2]), "r"(a[3]), "r"(b0), "r"(b1));
}
// split float2 into bf16x2 hi + bf16x2 residual
__device__ __forceinline__ void bfsplit(float2 v, unsigned& hi, unsigned& lo) {
    __nv_bfloat162 h = __floats2bfloat162_rn(v.x, v.y);
    float2 hf = __bfloat1622float2(h);
    __nv_bfloat162 l = __floats2bfloat162_rn(v.x - hf.x, v.y - hf.y);
    hi = *reinterpret_cast<unsigned*>(&h);
    lo = *reinterpret_cast<unsigned*>(&l);
}

// ---------------------------------------------------------------------------
// Kernel 0: W1/W2 -> tf32 fragment layouts.
// ---------------------------------------------------------------------------
__global__ __launch_bounds__(256) void prep_kernel(
    const float* __restrict__ w1, const float* __restrict__ w2)
{
    int i = blockIdx.x * 256 + threadIdx.x;     // 0..32767
    if (i < 16384) {
        int lane = i & 31, tp = (i >> 5) & 31, ks = i >> 10;
        int gid = lane >> 2, tig = lane & 3;
        int k0 = ks*8, n0 = (2*tp)*8, n1 = (2*tp+1)*8;
        float4 o;
        o.x = __uint_as_float(f2tf32(w1[(k0+tig)*FF   + n0+gid]));
        o.y = __uint_as_float(f2tf32(w1[(k0+tig+4)*FF + n0+gid]));
        o.z = __uint_as_float(f2tf32(w1[(k0+tig)*FF   + n1+gid]));
        o.w = __uint_as_float(f2tf32(w1[(k0+tig+4)*FF + n1+gid]));
        ((float4*)g_w1f)[i] = o;
    } else {
        int j = i - 16384;
        int lane = j & 31, tp = (j >> 5) & 7, ks = j >> 8;
        int gid = lane >> 2, tig = lane & 3;
        int k0 = ks*8, n0 = (2*tp)*8, n1 = (2*tp+1)*8;
        float4 o;
        o.x = __uint_as_float(f2tf32(w2[(k0+tig)*C   + n0+gid]));
        o.y = __uint_as_float(f2tf32(w2[(k0+tig+4)*C + n0+gid]));
        o.z = __uint_as_float(f2tf32(w2[(k0+tig)*C   + n1+gid]));
        o.w = __uint_as_float(f2tf32(w2[(k0+tig+4)*C + n1+gid]));
        ((float4*)g_w2f)[j] = o;
    }
}

// ---------------------------------------------------------------------------
// Kernel 1: per-head KQV projection with coalesced smem-staged stores.
// ---------------------------------------------------------------------------
__global__ __launch_bounds__(256) void proj_kernel(
    const float* __restrict__ feat_l, const float* __restrict__ feat_r,
    const float* __restrict__ kqv_w)
{
    __shared__ float sW[16*48];
    __shared__ float sO[8*548];
    int tid = threadIdx.x;
    for (int i = tid; i < 16*48; i += 256) sW[i] = kqv_w[i];

    int side = blockIdx.y;
    const float* feat = side ? feat_r : feat_l;
    int rl = tid >> 3;
    int h  = tid & 7;
    int row = blockIdx.x * 32 + rl;
    __syncthreads();

    float x[16];
    const float4* xp = (const float4*)(feat + (long)row*C + h*DH);
#pragma unroll
    for (int i = 0; i < 4; i++) {
        float4 t = xp[i];
        x[4*i+0]=t.x; x[4*i+1]=t.y; x[4*i+2]=t.z; x[4*i+3]=t.w;
    }
    float o[48];
#pragma unroll
    for (int j = 0; j < 48; j++) o[j] = 0.f;
#pragma unroll
    for (int i = 0; i < 16; i++) {
        float xi = x[i];
#pragma unroll
        for (int j = 0; j < 48; j++) o[j] = fmaf(xi, sW[i*48+j], o[j]);
    }

    int nn = row >> 8;
    int s0 = (blockIdx.x * 32) & 255;
    float* gdst[3] = { g_k[side], g_q[side], g_v[side] };

#pragma unroll
    for (int a = 0; a < 3; a++) {
        __syncthreads();
#pragma unroll
        for (int d = 0; d < 16; d++) sO[h*548 + rl*17 + d] = o[a*16 + d];
        __syncthreads();
        float* gp = gdst[a] + (((long)(nn*NH))*SW + s0) * DH;
        for (int j = tid; j < 4096; j += 256) {
            int hh = j >> 9, rem = j & 511, ss = rem >> 4, d = rem & 15;
            gp[(long)hh*SW*DH + ss*DH + d] = sO[hh*548 + ss*17 + d];
        }
    }
}

// ---------------------------------------------------------------------------
// Kernel 2: cross attention. QK: bf16 2-split m16n8k16 (3 terms, fp32-grade).
// AV: tf32 k8. prev/raw staged via smem; e->A-frag via quad shuffles.
// ---------------------------------------------------------------------------
#define PL 268    // sP pitch per l:  l*268 + h*33 + s
#define PK 172    // sK pitch per s:  s*172 + h*20 + d
#define PV 168    // sV pitch per s:  s*168 + h*20 + d
#define ATTN_SMEM ((32*PL + 32*PK + 32*PV)*4)   // 77824 B

__global__ __launch_bounds__(256, 2) void attn_kernel(
    const float* __restrict__ prev_l, const float* __restrict__ prev_r,
    float* __restrict__ d_out)
{
    extern __shared__ float sm[];
    float* sP = sm;                  // 32*268
    float* sK = sm + 32*PL;          // 32*172
    float* sV = sm + 32*PL + 32*PK;  // 32*168

    int tid = threadIdx.x;
    int lane = tid & 31;
    int h = tid >> 5;                // warp = head
    int gid = lane >> 2, tig = lane & 3;
    int lt = blockIdx.x, nn = blockIdx.y, side = blockIdx.z;
    int l0 = lt * 32;

    const float* prev = side ? prev_r : prev_l;
    float* raw = d_out + (side ? RAW_R : RAW_L);
    const float* qb = g_q[side];
    const float* kb = g_k[side ^ 1];
    const float* vb = g_v[side ^ 1];

    // ---- Q a-frags (k16 over full DH): a0..a3 = (row gid / gid+8) x (cols 2tig..,+8..)
    unsigned qhi[2][4], qlo[2][4];
    {
        const float* qbase = qb + (((long)(nn*NH + h))*SW + l0)*DH;
#pragma unroll
        for (int mt = 0; mt < 2; mt++) {
            const float* r0 = qbase + (mt*16 + gid)*DH;
            const float* r1 = r0 + 8*DH;
            bfsplit(*(const float2*)(r0 + 2*tig),     qhi[mt][0], qlo[mt][0]);
            bfsplit(*(const float2*)(r1 + 2*tig),     qhi[mt][1], qlo[mt][1]);
            bfsplit(*(const float2*)(r0 + 2*tig + 8), qhi[mt][2], qlo[mt][2]);
            bfsplit(*(const float2*)(r1 + 2*tig + 8), qhi[mt][3], qlo[mt][3]);
        }
    }

    float z00 = 0.f, z01 = 0.f, z10 = 0.f, z11 = 0.f;
    float acc[2][2][4];
#pragma unroll
    for (int mt = 0; mt < 2; mt++)
#pragma unroll
        for (int nt = 0; nt < 2; nt++)
#pragma unroll
            for (int j = 0; j < 4; j++) acc[mt][nt][j] = 0.f;

    for (int ch = 0; ch < 8; ch++) {
        int s0 = ch * 32;
        __syncthreads();

        // ---- stage prev chunk [32l][32s][8h] -> sP[l][h][s]
#pragma unroll
        for (int i = 0; i < 8; i++) {
            int f = i*256 + tid;
            int l = f >> 6, rem = f & 63;
            int s = rem >> 1, hb = (rem & 1) * 4;
            float4 pv = *(const float4*)(prev + (((long)(nn*SW + l0+l))*SW + s0+s)*NH + hb);
            float* dp = sP + l*PL + hb*33 + s;
            dp[0] = pv.x; dp[33] = pv.y; dp[66] = pv.z; dp[99] = pv.w;
        }
        // ---- stage K, V chunks
#pragma unroll
        for (int i = 0; i < 4; i++) {
            int f = i*256 + tid;
            int hh = f >> 7, rem = f & 127;
            int s = rem >> 2, dq = rem & 3;
            long src = (((long)(nn*NH + hh))*SW + s0 + s)*DH + dq*4;
            *(float4*)(sK + s*PK + hh*20 + dq*4) = *(const float4*)(kb + src);
            *(float4*)(sV + s*PV + hh*20 + dq*4) = *(const float4*)(vb + src);
        }
        __syncthreads();

        // ---- QK mma (bf16 split, k16): c[mt][st][4]
        float c[2][4][4];
#pragma unroll
        for (int mt = 0; mt < 2; mt++)
#pragma unroll
            for (int st = 0; st < 4; st++)
#pragma unroll
                for (int j = 0; j < 4; j++) c[mt][st][j] = 0.f;

#pragma unroll
        for (int st = 0; st < 4; st++) {
            const float* kr = sK + (st*8 + gid)*PK + h*20;
            unsigned k0h, k0l, k1h, k1l;
            bfsplit(*(const float2*)(kr + 2*tig),     k0h, k0l);
            bfsplit(*(const float2*)(kr + 2*tig + 8), k1h, k1l);
#pragma unroll
            for (int mt = 0; mt < 2; mt++) {
                mma_bf16(c[mt][st], qhi[mt], k0h, k1h);
                mma_bf16(c[mt][st], qhi[mt], k0l, k1l);
                mma_bf16(c[mt][st], qlo[mt], k0h, k1h);
            }
        }

        // ---- prev add, raw (in sP), exp, z
#pragma unroll
        for (int mt = 0; mt < 2; mt++) {
#pragma unroll
            for (int st = 0; st < 4; st++) {
                float* pp = sP + (mt*16 + gid)*PL + h*33 + st*8 + 2*tig;
                float r0 = c[mt][st][0] + pp[0];
                float r1 = c[mt][st][1] + pp[1];
                float r2 = c[mt][st][2] + pp[8*PL];
                float r3 = c[mt][st][3] + pp[8*PL + 1];
                pp[0] = r0; pp[1] = r1; pp[8*PL] = r2; pp[8*PL + 1] = r3;
                float e0 = __expf(0.25f*r0), e1 = __expf(0.25f*r1);
                float e2 = __expf(0.25f*r2), e3 = __expf(0.25f*r3);
                if (mt == 0) { z00 += e0 + e1; z01 += e2 + e3; }
                else         { z10 += e0 + e1; z11 += e2 + e3; }
                c[mt][st][0] = e0; c[mt][st][1] = e1; c[mt][st][2] = e2; c[mt][st][3] = e3;
            }
        }

        // ---- AV mma (tf32 k8)
        int srcA = (lane & 28) | (tig >> 1);
        int srcB = srcA + 2;
        bool odd = (tig & 1);
#pragma unroll
        for (int st = 0; st < 4; st++) {
            unsigned a[2][4];
#pragma unroll
            for (int mt = 0; mt < 2; mt++) {
                float e0 = c[mt][st][0], e1 = c[mt][st][1];
                float e2 = c[mt][st][2], e3 = c[mt][st][3];
                float g00 = __shfl_sync(0xffffffffu, e0, srcA);
                float g01 = __shfl_sync(0xffffffffu, e1, srcA);
                float g20 = __shfl_sync(0xffffffffu, e2, srcA);
                float g21 = __shfl_sync(0xffffffffu, e3, srcA);
                float h00 = __shfl_sync(0xffffffffu, e0, srcB);
                float h01 = __shfl_sync(0xffffffffu, e1, srcB);
                float h20 = __shfl_sync(0xffffffffu, e2, srcB);
                float h21 = __shfl_sync(0xffffffffu, e3, srcB);
                a[mt][0] = f2tf32(odd ? g01 : g00);
                a[mt][1] = f2tf32(odd ? g21 : g20);
                a[mt][2] = f2tf32(odd ? h01 : h00);
                a[mt][3] = f2tf32(odd ? h21 : h20);
            }
            const float* vr0 = sV + (st*8 + tig)*PV + h*20;
            const float* vr1 = sV + (st*8 + tig + 4)*PV + h*20;
#pragma unroll
            for (int nt = 0; nt < 2; nt++) {
                unsigned vb0 = f2tf32(vr0[nt*8 + gid]);
                unsigned vb1 = f2tf32(vr1[nt*8 + gid]);
                mma_tf32(acc[0][nt], a[0][0], a[0][1], a[0][2], a[0][3], vb0, vb1);
                mma_tf32(acc[1][nt], a[1][0], a[1][1], a[1][2], a[1][3], vb0, vb1);
            }
        }

        // ---- raw out: sP -> gmem (coalesced)
        __syncthreads();
#pragma unroll
        for (int i = 0; i < 8; i++) {
            int f = i*256 + tid;
            int l = f >> 6, rem = f & 63;
            int s = rem >> 1, hb = (rem & 1) * 4;
            float* dp = sP + l*PL + hb*33 + s;
            float4 rv = make_float4(dp[0], dp[33], dp[66], dp[99]);
            *(float4*)(raw + (((long)(nn*SW + l0+l))*SW + s0+s)*NH + hb) = rv;
        }
    }

    // ---- z quad-reduce
    z00 += __shfl_xor_sync(0xffffffffu, z00, 1); z00 += __shfl_xor_sync(0xffffffffu, z00, 2);
    z01 += __shfl_xor_sync(0xffffffffu, z01, 1); z01 += __shfl_xor_sync(0xffffffffu, z01, 2);
    z10 += __shfl_xor_sync(0xffffffffu, z10, 1); z10 += __shfl_xor_sync(0xffffffffu, z10, 2);
    z11 += __shfl_xor_sync(0xffffffffu, z11, 1); z11 += __shfl_xor_sync(0xffffffffu, z11, 2);
    float iz[2][2] = { {1.f/z00, 1.f/z01}, {1.f/z10, 1.f/z11} };

    // ---- msg out
    float* mb = g_msg[side];
#pragma unroll
    for (int mt = 0; mt < 2; mt++) {
#pragma unroll
        for (int nt = 0; nt < 2; nt++) {
            long base = ((long)(nn*SW + l0 + mt*16 + gid))*C + h*DH + nt*8 + 2*tig;
            *(float2*)(mb + base)       = make_float2(acc[mt][nt][0]*iz[mt][0], acc[mt][nt][1]*iz[mt][0]);
            *(float2*)(mb + base + 8*C) = make_float2(acc[mt][nt][2]*iz[mt][1], acc[mt][nt][3]*iz[mt][1]);
        }
    }
}

// ---------------------------------------------------------------------------
// Kernel 3: fused LN1 + FFN (tf32 mma) + residual + LN2. 32 rows/block.
// Re-tiled: each warp owns a UNIQUE col slice (64 cols GEMM1 / 16 cols GEMM2)
// across all 32 rows -> no duplicate B-fragment loads.
// ---------------------------------------------------------------------------
#define XPITCH 132
#define HPITCH 516

__global__ __launch_bounds__(256, 2) void ffn_kernel(
    const float* __restrict__ feat_l, const float* __restrict__ feat_r,
    const float* __restrict__ b1, const float* __restrict__ b2,
    const float* __restrict__ lg1, const float* __restrict__ lb1,
    const float* __restrict__ lg2, const float* __restrict__ lb2,
    float* __restrict__ d_out)
{
    extern __shared__ float smem[];
    float* sX = smem;
    float* sH = smem + 32*XPITCH;
    int tid  = threadIdx.x;
    int side = blockIdx.y;
    const float* feat = side ? feat_r : feat_l;
    const float* msg  = g_msg[side];
    float* outp = d_out + (side ? OUT_R : OUT_L);
    int row0 = blockIdx.x * 32;
    int warp = tid >> 5, lane = tid & 31;
    int gid = lane >> 2, tig = lane & 3;

    for (int j = tid; j < 1024; j += 256) {
        int r = j >> 5, c4 = j & 31;
        long gi = ((long)(row0+r))*C + c4*4;
        float4 a = *(const float4*)(feat + gi);
        float4 b = *(const float4*)(msg + gi);
        a.x += b.x; a.y += b.y; a.z += b.z; a.w += b.w;
        *(float4*)(&sX[r*XPITCH + c4*4]) = a;
    }
    __syncthreads();

#pragma unroll
    for (int rr = 0; rr < 4; rr++) {
        int r = warp*4 + rr;
        float v0 = sX[r*XPITCH+lane],    v1 = sX[r*XPITCH+lane+32];
        float v2 = sX[r*XPITCH+lane+64], v3 = sX[r*XPITCH+lane+96];
        float sum = v0+v1+v2+v3;
        float sq  = v0*v0+v1*v1+v2*v2+v3*v3;
        for (int o = 16; o; o >>= 1) {
            sum += __shfl_xor_sync(~0u, sum, o);
            sq  += __shfl_xor_sync(~0u, sq,  o);
        }
        float mu = sum*(1.f/128.f);
        float rs = rsqrtf(sq*(1.f/128.f) - mu*mu + 1e-5f);
        sX[r*XPITCH+lane]    = (v0-mu)*rs*lg1[lane]    + lb1[lane];
        sX[r*XPITCH+lane+32] = (v1-mu)*rs*lg1[lane+32] + lb1[lane+32];
        sX[r*XPITCH+lane+64] = (v2-mu)*rs*lg1[lane+64] + lb1[lane+64];
        sX[r*XPITCH+lane+96] = (v3-mu)*rs*lg1[lane+96] + lb1[lane+96];
    }
    __syncthreads();

    // GEMM1: warp = cols [warp*64, +64) x rows 0..31 (mt = m16 half)
    {
        float acc[2][8][4];
#pragma unroll
        for (int mt = 0; mt < 2; mt++)
#pragma unroll
            for (int t = 0; t < 8; t++)
#pragma unroll
                for (int j = 0; j < 4; j++) acc[mt][t][j] = 0.f;

#pragma unroll 2
        for (int ks = 0; ks < 16; ks++) {
            int k0 = ks*8;
            unsigned a[2][4];
#pragma unroll
            for (int mt = 0; mt < 2; mt++) {
                a[mt][0] = f2tf32(sX[(mt*16+gid)*XPITCH   + k0 + tig]);
                a[mt][1] = f2tf32(sX[(mt*16+gid+8)*XPITCH + k0 + tig]);
                a[mt][2] = f2tf32(sX[(mt*16+gid)*XPITCH   + k0 + tig + 4]);
                a[mt][3] = f2tf32(sX[(mt*16+gid+8)*XPITCH + k0 + tig + 4]);
            }
            const float4* bp = (const float4*)g_w1f + (ks*32 + warp*4)*32 + lane;
#pragma unroll
            for (int j4 = 0; j4 < 4; j4++) {
                float4 b = bp[j4*32];
#pragma unroll
                for (int mt = 0; mt < 2; mt++) {
                    mma_tf32(acc[mt][2*j4],   a[mt][0],a[mt][1],a[mt][2],a[mt][3], __float_as_uint(b.x), __float_as_uint(b.y));
                    mma_tf32(acc[mt][2*j4+1], a[mt][0],a[mt][1],a[mt][2],a[mt][3], __float_as_uint(b.z), __float_as_uint(b.w));
                }
            }
        }
#pragma unroll
        for (int mt = 0; mt < 2; mt++) {
#pragma unroll
            for (int t = 0; t < 8; t++) {
                int col = warp*64 + t*8 + 2*tig;
                int r0 = mt*16 + gid, r1 = r0 + 8;
                float h00 = acc[mt][t][0] + b1[col];
                float h01 = acc[mt][t][1] + b1[col+1];
                float h10 = acc[mt][t][2] + b1[col];
                float h11 = acc[mt][t][3] + b1[col+1];
                h00 = 0.5f*h00*(1.f + erff(h00*0.70710678118654752f));
                h01 = 0.5f*h01*(1.f + erff(h01*0.70710678118654752f));
                h10 = 0.5f*h10*(1.f + erff(h10*0.70710678118654752f));
                h11 = 0.5f*h11*(1.f + erff(h11*0.70710678118654752f));
                *(float2*)(&sH[r0*HPITCH + col]) =
                    make_float2(__uint_as_float(f2tf32(h00)), __uint_as_float(f2tf32(h01)));
                *(float2*)(&sH[r1*HPITCH + col]) =
                    make_float2(__uint_as_float(f2tf32(h10)), __uint_as_float(f2tf32(h11)));
            }
        }
    }
    __syncthreads();

    // GEMM2: warp = cols [warp*16, +16) x rows 0..31
    float acc2[2][2][4];
#pragma unroll
    for (int mt = 0; mt < 2; mt++)
#pragma unroll
        for (int nt = 0; nt < 2; nt++)
#pragma unroll
            for (int j = 0; j < 4; j++) acc2[mt][nt][j] = 0.f;
    {
        const unsigned* sHi = (const unsigned*)sH;
#pragma unroll 4
        for (int ks = 0; ks < 64; ks++) {
            int k0 = ks*8;
            unsigned a[2][4];
#pragma unroll
            for (int mt = 0; mt < 2; mt++) {
                a[mt][0] = sHi[(mt*16+gid)*HPITCH   + k0 + tig];
                a[mt][1] = sHi[(mt*16+gid+8)*HPITCH + k0 + tig];
                a[mt][2] = sHi[(mt*16+gid)*HPITCH   + k0 + tig + 4];
                a[mt][3] = sHi[(mt*16+gid+8)*HPITCH + k0 + tig + 4];
            }
            float4 b = ((const float4*)g_w2f)[(ks*8 + warp)*32 + lane];
#pragma unroll
            for (int mt = 0; mt < 2; mt++) {
                mma_tf32(acc2[mt][0], a[mt][0],a[mt][1],a[mt][2],a[mt][3], __float_as_uint(b.x), __float_as_uint(b.y));
                mma_tf32(acc2[mt][1], a[mt][0],a[mt][1],a[mt][2],a[mt][3], __float_as_uint(b.z), __float_as_uint(b.w));
            }
        }
    }
    __syncthreads();   // reads of sH done; reuse as out tile

#pragma unroll
    for (int mt = 0; mt < 2; mt++) {
#pragma unroll
        for (int nt = 0; nt < 2; nt++) {
            int col = warp*16 + nt*8 + 2*tig;
            int r0 = mt*16 + gid, r1 = r0 + 8;
            float2 lo, hi;
            lo.x = acc2[mt][nt][0] + b2[col]   + sX[r0*XPITCH + col];
            lo.y = acc2[mt][nt][1] + b2[col+1] + sX[r0*XPITCH + col + 1];
            hi.x = acc2[mt][nt][2] + b2[col]   + sX[r1*XPITCH + col];
            hi.y = acc2[mt][nt][3] + b2[col+1] + sX[r1*XPITCH + col + 1];
            *(float2*)(&sH[r0*XPITCH + col]) = lo;
            *(float2*)(&sH[r1*XPITCH + col]) = hi;
        }
    }
    __syncthreads();

#pragma unroll
    for (int rr = 0; rr < 4; rr++) {
        int r = warp*4 + rr;
        float v0 = sH[r*XPITCH+lane],    v1 = sH[r*XPITCH+lane+32];
        float v2 = sH[r*XPITCH+lane+64], v3 = sH[r*XPITCH+lane+96];
        float sum = v0+v1+v2+v3;
        float sq  = v0*v0+v1*v1+v2*v2+v3*v3;
        for (int o = 16; o; o >>= 1) {
            sum += __shfl_xor_sync(~0u, sum, o);
            sq  += __shfl_xor_sync(~0u, sq,  o);
        }
        float mu = sum*(1.f/128.f);
        float rs = rsqrtf(sq*(1.f/128.f) - mu*mu + 1e-5f);
        long go = ((long)(row0+r))*C;
        outp[go+lane]    = (v0-mu)*rs*lg2[lane]    + lb2[lane];
        outp[go+lane+32] = (v1-mu)*rs*lg2[lane+32] + lb2[lane+32];
        outp[go+lane+64] = (v2-mu)*rs*lg2[lane+64] + lb2[lane+64];
        outp[go+lane+96] = (v3-mu)*rs*lg2[lane+96] + lb2[lane+96];
    }
}

// ---------------------------------------------------------------------------
extern "C" void kernel_launch(void* const* d_in, const int* in_sizes, int n_in,
                              void* d_out, int out_size)
{
    const float* feat_l = (const float*)d_in[0];
    const float* feat_r = (const float*)d_in[1];
    const float* prev_l = (const float*)d_in[2];
    const float* prev_r = (const float*)d_in[3];
    const float* kqv_w  = (const float*)d_in[4];
    const float* ff_w1  = (const float*)d_in[5];
    const float* ff_b1  = (const float*)d_in[6];
    const float* ff_w2  = (const float*)d_in[7];
    const float* ff_b2  = (const float*)d_in[8];
    const float* ln1_g  = (const float*)d_in[9];
    const float* ln1_b  = (const float*)d_in[10];
    const float* ln2_g  = (const float*)d_in[11];
    const float* ln2_b  = (const float*)d_in[12];
    float* out = (float*)d_out;

    const int FFN_SMEM = (32*XPITCH + 32*HPITCH) * 4;   // 82944 B
    cudaFuncSetAttribute(ffn_kernel, cudaFuncAttributeMaxDynamicSharedMemorySize, FFN_SMEM);
    cudaFuncSetAttribute(attn_kernel, cudaFuncAttributeMaxDynamicSharedMemorySize, ATTN_SMEM);

    prep_kernel<<<128, 256>>>(ff_w1, ff_w2);
    proj_kernel<<<dim3(NTOK/32, 2), 256>>>(feat_l, feat_r, kqv_w);
    attn_kernel<<<dim3(SW/32, NSEQ, 2), 256, ATTN_SMEM>>>(prev_l, prev_r, out);
    ffn_kernel<<<dim3(NTOK/32, 2), 256, FFN_SMEM>>>(
        feat_l, feat_r, ff_b1, ff_b2,
        ln1_g, ln1_b, ln2_g, ln2_b, out);
}